// round 1
// baseline (speedup 1.0000x reference)
#include <cuda_runtime.h>
#include <cuda_bf16.h>
#include <math.h>

// Problem constants (fixed shapes)
#define LQ 2048     // seq len
#define HQ 2048     // hidden
#define EQ 4096     // intermediate
#define NQ 16       // ssm state
#define KQ 4        // conv kernel
#define RQ 128      // dt rank
#define PQ 160      // R + 2N

// ---------------------------------------------------------------------------
// Scratch (device globals; no allocation allowed)
// ---------------------------------------------------------------------------
__device__ float g_xz [LQ * 2 * EQ];   // in_proj output: [:, :E]=pre-conv h, [:, E:]=gate  (64MB)
__device__ float g_h  [LQ * EQ];       // conv+silu output                                   (32MB)
__device__ float g_ssm[LQ * PQ];       // x_proj output: dt_raw | B | C                      (1.3MB)
__device__ float g_dt [LQ * EQ];       // softplus(dt_raw @ dt_proj_w^T + b)                 (32MB)
__device__ float g_y  [LQ * EQ];       // scan output (gated)                                (32MB)

// ---------------------------------------------------------------------------
// Generic NT GEMM: C[M,N] = epi( A[M,K] * B[N,K]^T )
// BM=BN=128, BK=16, 256 threads, 8x8 register tile per thread.
// M must be a multiple of 128 (true for all call sites: M=2048).
// N,K handled with guards (K multiple of 16 at all call sites).
// EPI: 0 = plain store, 1 = softplus(x + bias[n])
// ---------------------------------------------------------------------------
#define BM 128
#define BN 128
#define BKK 16

template <int EPI>
__global__ void __launch_bounds__(256, 2)
gemm_nt(const float* __restrict__ A, const float* __restrict__ B,
        float* __restrict__ C, int M, int N, int Kdim,
        int lda, int ldb, int ldc, const float* __restrict__ bias)
{
    __shared__ float As[BKK][BM + 4];
    __shared__ float Bs[BKK][BN + 4];

    const int bm = blockIdx.y * BM;
    const int bn = blockIdx.x * BN;
    const int tid = threadIdx.x;
    const int tm = tid >> 4;       // 0..15
    const int tn = tid & 15;       // 0..15

    float acc[8][8];
#pragma unroll
    for (int i = 0; i < 8; ++i)
#pragma unroll
        for (int j = 0; j < 8; ++j) acc[i][j] = 0.f;

    for (int k0 = 0; k0 < Kdim; k0 += BKK) {
        // ---- load A tile (rows always valid) ----
#pragma unroll
        for (int it = 0; it < 2; ++it) {
            int v   = tid + it * 256;       // 0..511 vec id
            int row = v >> 2;               // 0..127
            int c4  = (v & 3) << 2;         // 0,4,8,12
            const float4 av = *reinterpret_cast<const float4*>(
                &A[(size_t)(bm + row) * lda + k0 + c4]);
            As[c4 + 0][row] = av.x;
            As[c4 + 1][row] = av.y;
            As[c4 + 2][row] = av.z;
            As[c4 + 3][row] = av.w;
        }
        // ---- load B tile (row guard for N not multiple of 128) ----
#pragma unroll
        for (int it = 0; it < 2; ++it) {
            int v   = tid + it * 256;
            int row = v >> 2;
            int c4  = (v & 3) << 2;
            float4 bv = make_float4(0.f, 0.f, 0.f, 0.f);
            int gn = bn + row;
            if (gn < N)
                bv = *reinterpret_cast<const float4*>(
                    &B[(size_t)gn * ldb + k0 + c4]);
            Bs[c4 + 0][row] = bv.x;
            Bs[c4 + 1][row] = bv.y;
            Bs[c4 + 2][row] = bv.z;
            Bs[c4 + 3][row] = bv.w;
        }
        __syncthreads();

#pragma unroll
        for (int k = 0; k < BKK; ++k) {
            float4 ra0 = *reinterpret_cast<const float4*>(&As[k][tm * 8]);
            float4 ra1 = *reinterpret_cast<const float4*>(&As[k][tm * 8 + 4]);
            float4 rb0 = *reinterpret_cast<const float4*>(&Bs[k][tn * 8]);
            float4 rb1 = *reinterpret_cast<const float4*>(&Bs[k][tn * 8 + 4]);
            float ra[8] = {ra0.x, ra0.y, ra0.z, ra0.w, ra1.x, ra1.y, ra1.z, ra1.w};
            float rb[8] = {rb0.x, rb0.y, rb0.z, rb0.w, rb1.x, rb1.y, rb1.z, rb1.w};
#pragma unroll
            for (int i = 0; i < 8; ++i)
#pragma unroll
                for (int j = 0; j < 8; ++j)
                    acc[i][j] = fmaf(ra[i], rb[j], acc[i][j]);
        }
        __syncthreads();
    }

    // ---- epilogue ----
#pragma unroll
    for (int i = 0; i < 8; ++i) {
        int gm = bm + tm * 8 + i;
#pragma unroll
        for (int j = 0; j < 8; ++j) {
            int gn = bn + tn * 8 + j;
            if (gn < N) {
                float v = acc[i][j];
                if (EPI == 1) {
                    v += bias[gn];
                    // stable softplus = max(v,0) + log1p(exp(-|v|))
                    v = fmaxf(v, 0.f) + log1pf(__expf(-fabsf(v)));
                }
                C[(size_t)gm * ldc + gn] = v;
            }
        }
    }
}

// ---------------------------------------------------------------------------
// Depthwise causal conv (K=4, left pad 3) + bias + SiLU
// h[l,e] = silu( sum_k w[e,k] * x[l-3+k, e] + b[e] ),  x = g_xz[:, :E]
// ---------------------------------------------------------------------------
__global__ void __launch_bounds__(256)
conv_silu_kernel(const float* __restrict__ xz, const float* __restrict__ w,
                 const float* __restrict__ b, float* __restrict__ h)
{
    int e = blockIdx.x * 256 + threadIdx.x;   // 0..E-1
    int l = blockIdx.y;                        // 0..L-1
    float acc = b[e];
#pragma unroll
    for (int k = 0; k < KQ; ++k) {
        int ls = l - (KQ - 1) + k;
        if (ls >= 0)
            acc = fmaf(w[e * KQ + k], xz[(size_t)ls * (2 * EQ) + e], acc);
    }
    float sg = 1.f / (1.f + __expf(-acc));
    h[(size_t)l * EQ + e] = acc * sg;
}

// ---------------------------------------------------------------------------
// Selective scan. 256 threads = 16 e-channels x 16 n-lanes per block.
// Each 16-lane group owns one e; scans L=2048 steps serially.
// y[l,e] = (sum_n s_n * C[l,n] + h[l,e]*D[e]) * silu(gate[l,e])
// ---------------------------------------------------------------------------
__global__ void __launch_bounds__(256)
scan_kernel(const float* __restrict__ dt, const float* __restrict__ h,
            const float* __restrict__ ssm, const float* __restrict__ xz,
            const float* __restrict__ A_log, const float* __restrict__ Dp,
            float* __restrict__ y)
{
    int tid = threadIdx.x;
    int n   = tid & 15;
    int el  = tid >> 4;
    int e   = blockIdx.x * 16 + el;

    float a = -__expf(A_log[e * NQ + n]);   // A[e,n]
    float d = Dp[e];
    float s = 0.f;

    for (int l = 0; l < LQ; ++l) {
        float dtv = dt[(size_t)l * EQ + e];
        float hv  = h [(size_t)l * EQ + e];
        float Bv  = ssm[l * PQ + RQ + n];
        float Cv  = ssm[l * PQ + RQ + NQ + n];

        float dA = __expf(dtv * a);
        s = fmaf(s, dA, (dtv * hv) * Bv);

        float p = s * Cv;
#pragma unroll
        for (int off = 8; off; off >>= 1)
            p += __shfl_xor_sync(0xffffffffu, p, off, 16);

        if (n == 0) {
            float g  = xz[(size_t)l * (2 * EQ) + EQ + e];
            float sg = g / (1.f + __expf(-g));
            y[(size_t)l * EQ + e] = (p + hv * d) * sg;
        }
    }
}

// ---------------------------------------------------------------------------
// Launcher
// ---------------------------------------------------------------------------
extern "C" void kernel_launch(void* const* d_in, const int* in_sizes, int n_in,
                              void* d_out, int out_size)
{
    const float* hidden     = (const float*)d_in[0];
    const float* in_proj_w  = (const float*)d_in[1];
    const float* conv_w     = (const float*)d_in[2];
    const float* conv_b     = (const float*)d_in[3];
    const float* x_proj_w   = (const float*)d_in[4];
    const float* dt_proj_w  = (const float*)d_in[5];
    const float* dt_proj_b  = (const float*)d_in[6];
    const float* A_log      = (const float*)d_in[7];
    const float* Dp         = (const float*)d_in[8];
    const float* out_proj_w = (const float*)d_in[9];
    float* out = (float*)d_out;

    float *xz, *h, *ssmp, *dt, *y;
    cudaGetSymbolAddress((void**)&xz,   g_xz);
    cudaGetSymbolAddress((void**)&h,    g_h);
    cudaGetSymbolAddress((void**)&ssmp, g_ssm);
    cudaGetSymbolAddress((void**)&dt,   g_dt);
    cudaGetSymbolAddress((void**)&y,    g_y);

    // 1) in_proj: [L,H] @ [2E,H]^T -> g_xz [L,2E]
    gemm_nt<0><<<dim3(2 * EQ / BN, LQ / BM), 256>>>(
        hidden, in_proj_w, xz, LQ, 2 * EQ, HQ, HQ, HQ, 2 * EQ, nullptr);

    // 2) depthwise conv + SiLU -> g_h [L,E]
    conv_silu_kernel<<<dim3(EQ / 256, LQ), 256>>>(xz, conv_w, conv_b, h);

    // 3) x_proj: [L,E] @ [160,E]^T -> g_ssm [L,160]
    gemm_nt<0><<<dim3((PQ + BN - 1) / BN, LQ / BM), 256>>>(
        h, x_proj_w, ssmp, LQ, PQ, EQ, EQ, EQ, PQ, nullptr);

    // 4) dt_proj: [L,128] (strided in g_ssm) @ [E,128]^T + b, softplus -> g_dt [L,E]
    gemm_nt<1><<<dim3(EQ / BN, LQ / BM), 256>>>(
        ssmp, dt_proj_w, dt, LQ, EQ, RQ, PQ, RQ, EQ, dt_proj_b);

    // 5) selective scan + D skip + gate -> g_y [L,E]
    scan_kernel<<<EQ / 16, 256>>>(dt, h, ssmp, xz, A_log, Dp, y);

    // 6) out_proj: [L,E] @ [H,E]^T -> out [L,H]
    gemm_nt<0><<<dim3(HQ / BN, LQ / BM), 256>>>(
        y, out_proj_w, out, LQ, HQ, EQ, EQ, EQ, HQ, nullptr);
}

// round 2
// speedup vs baseline: 1.4107x; 1.4107x over previous
#include <cuda_runtime.h>
#include <cuda_bf16.h>
#include <math.h>
#include <stdint.h>

// Problem constants (fixed shapes)
#define LQ 2048     // seq len
#define HQ 2048     // hidden
#define EQ 4096     // intermediate
#define NQ 16       // ssm state
#define KQ 4        // conv kernel
#define RQ 128      // dt rank
#define PQ 160      // R + 2N

// ---------------------------------------------------------------------------
// Scratch (device globals; no allocation allowed)
// ---------------------------------------------------------------------------
__device__ float g_xz [LQ * 2 * EQ];   // in_proj output (64MB)
__device__ float g_h  [LQ * EQ];       // conv+silu output
__device__ float g_ssm[LQ * PQ];       // x_proj output: dt_raw | B | C
__device__ float g_dt [LQ * EQ];       // softplus(dt)
__device__ float g_y  [LQ * EQ];       // scan output (gated)

// bf16 split buffers (hi/lo)
__device__ __nv_bfloat16 g_hid_hi [LQ * HQ],      g_hid_lo [LQ * HQ];
__device__ __nv_bfloat16 g_win_hi [2 * EQ * HQ],  g_win_lo [2 * EQ * HQ];
__device__ __nv_bfloat16 g_hb_hi  [LQ * EQ],      g_hb_lo  [LQ * EQ];
__device__ __nv_bfloat16 g_wx_hi  [PQ * EQ],      g_wx_lo  [PQ * EQ];
__device__ __nv_bfloat16 g_dtr_hi [LQ * RQ],      g_dtr_lo [LQ * RQ];
__device__ __nv_bfloat16 g_wdt_hi [EQ * RQ],      g_wdt_lo [EQ * RQ];
__device__ __nv_bfloat16 g_yb_hi  [LQ * EQ],      g_yb_lo  [LQ * EQ];
__device__ __nv_bfloat16 g_wout_hi[HQ * EQ],      g_wout_lo[HQ * EQ];

// ---------------------------------------------------------------------------
// fp32 -> bf16 hi/lo split
// ---------------------------------------------------------------------------
__global__ void __launch_bounds__(256)
split_kernel(const float* __restrict__ x, __nv_bfloat16* __restrict__ hi,
             __nv_bfloat16* __restrict__ lo, int n)
{
    int i = blockIdx.x * 256 + threadIdx.x;
    if (i < n) {
        float v = x[i];
        __nv_bfloat16 h = __float2bfloat16(v);
        hi[i] = h;
        lo[i] = __float2bfloat16(v - __bfloat162float(h));
    }
}

// strided variant: extract [rows x cols] from src with row stride srcld
__global__ void __launch_bounds__(256)
split_strided_kernel(const float* __restrict__ x, __nv_bfloat16* __restrict__ hi,
                     __nv_bfloat16* __restrict__ lo, int rows, int cols, int srcld)
{
    int i = blockIdx.x * 256 + threadIdx.x;
    if (i < rows * cols) {
        int r = i / cols, c = i - r * cols;
        float v = x[(size_t)r * srcld + c];
        __nv_bfloat16 h = __float2bfloat16(v);
        hi[i] = h;
        lo[i] = __float2bfloat16(v - __bfloat162float(h));
    }
}

// ---------------------------------------------------------------------------
// bf16 split-3 tensor-core GEMM:  C[M,N] = epi( A[M,K] * B[N,K]^T )
// where A ~= Ahi + Alo, B ~= Bhi + Blo and C = Ahi*Bhi + Ahi*Blo + Alo*Bhi.
// BM=128, BN=128, BK=32, 256 threads (8 warps 2x4, warp tile 64x32).
// cp.async 2-stage double buffer. lda = ldb = Kdim (compact).
// EPI: 0 plain, 1 softplus(x + bias[n]).
// ---------------------------------------------------------------------------
#define SM_STRIDE 40                 // bf16 elems per smem row (padded from 32)
#define MAT_ELEMS (128 * SM_STRIDE)  // 5120 bf16 per matrix tile
#define STAGE_ELEMS (4 * MAT_ELEMS)  // Ahi,Alo,Bhi,Blo
#define GEMM_SMEM_BYTES (2 * STAGE_ELEMS * 2)

#define MMA_BF16(c, A, B)                                                   \
    asm volatile(                                                           \
        "mma.sync.aligned.m16n8k16.row.col.f32.bf16.bf16.f32 "              \
        "{%0,%1,%2,%3}, {%4,%5,%6,%7}, {%8,%9}, {%0,%1,%2,%3};\n"           \
        : "+f"(c[0]), "+f"(c[1]), "+f"(c[2]), "+f"(c[3])                    \
        : "r"(A[0]), "r"(A[1]), "r"(A[2]), "r"(A[3]), "r"(B[0]), "r"(B[1]))

__device__ __forceinline__ void gemm_issue_stage(
    uint32_t sbase, int stage, int kt,
    const __nv_bfloat16* Ahi, const __nv_bfloat16* Alo,
    const __nv_bfloat16* Bhi, const __nv_bfloat16* Blo,
    int bm, int bn, int N, int Kdim, int tid)
{
    int k0 = kt << 5;
#pragma unroll
    for (int c = 0; c < 8; ++c) {
        int idx = c * 256 + tid;          // 0..2047
        int mat = idx >> 9;               // 0..3
        int rem = idx & 511;
        int row = rem >> 2;               // 0..127
        int cv  = (rem & 3) << 3;         // bf16 col offset: 0,8,16,24
        uint32_t dst = sbase +
            (uint32_t)((stage * STAGE_ELEMS + mat * MAT_ELEMS + row * SM_STRIDE + cv) * 2);
        const __nv_bfloat16* gsrc;
        int vbytes = 16;
        if (mat == 0)      gsrc = Ahi + (size_t)(bm + row) * Kdim + k0 + cv;
        else if (mat == 1) gsrc = Alo + (size_t)(bm + row) * Kdim + k0 + cv;
        else {
            int r = bn + row;
            if (r >= N) { vbytes = 0; r = N - 1; }
            gsrc = (mat == 2 ? Bhi : Blo) + (size_t)r * Kdim + k0 + cv;
        }
        asm volatile("cp.async.cg.shared.global [%0], [%1], 16, %2;\n"
                     :: "r"(dst), "l"(gsrc), "r"(vbytes));
    }
    asm volatile("cp.async.commit_group;\n");
}

template <int EPI>
__global__ void __launch_bounds__(256, 1)
gemm_bf3(const __nv_bfloat16* __restrict__ Ahi, const __nv_bfloat16* __restrict__ Alo,
         const __nv_bfloat16* __restrict__ Bhi, const __nv_bfloat16* __restrict__ Blo,
         float* __restrict__ C, int N, int Kdim, int ldc,
         const float* __restrict__ bias)
{
    extern __shared__ __nv_bfloat16 smbuf[];
    const uint32_t sbase = (uint32_t)__cvta_generic_to_shared(smbuf);

    const int tid  = threadIdx.x;
    const int warp = tid >> 5, lane = tid & 31;
    const int wm = warp >> 2, wn = warp & 3;   // 2 x 4 warps
    const int g  = lane >> 2;                  // 0..7
    const int kp = (lane & 3) << 1;            // 0,2,4,6
    const int bm = blockIdx.y * 128, bn = blockIdx.x * 128;

    float acc[4][4][4];
#pragma unroll
    for (int mt = 0; mt < 4; ++mt)
#pragma unroll
        for (int nt = 0; nt < 4; ++nt)
#pragma unroll
            for (int q = 0; q < 4; ++q) acc[mt][nt][q] = 0.f;

    const int KT = Kdim >> 5;

    gemm_issue_stage(sbase, 0, 0, Ahi, Alo, Bhi, Blo, bm, bn, N, Kdim, tid);

    for (int kt = 0; kt < KT; ++kt) {
        if (kt + 1 < KT) {
            gemm_issue_stage(sbase, (kt + 1) & 1, kt + 1, Ahi, Alo, Bhi, Blo,
                             bm, bn, N, Kdim, tid);
            asm volatile("cp.async.wait_group 1;\n");
        } else {
            asm volatile("cp.async.wait_group 0;\n");
        }
        __syncthreads();

        const __nv_bfloat16* base = smbuf + (kt & 1) * STAGE_ELEMS;
        const __nv_bfloat16* sAhi = base;
        const __nv_bfloat16* sAlo = base + MAT_ELEMS;
        const __nv_bfloat16* sBhi = base + 2 * MAT_ELEMS;
        const __nv_bfloat16* sBlo = base + 3 * MAT_ELEMS;

#pragma unroll
        for (int kk = 0; kk < 32; kk += 16) {
            uint32_t Ah[4][4], Al[4][4], Bh[4][2], Bl[4][2];
#pragma unroll
            for (int mt = 0; mt < 4; ++mt) {
                int r = wm * 64 + mt * 16 + g;
                int o = r * SM_STRIDE + kk + kp;
                Ah[mt][0] = *(const uint32_t*)(sAhi + o);
                Ah[mt][1] = *(const uint32_t*)(sAhi + o + 8 * SM_STRIDE);
                Ah[mt][2] = *(const uint32_t*)(sAhi + o + 8);
                Ah[mt][3] = *(const uint32_t*)(sAhi + o + 8 * SM_STRIDE + 8);
                Al[mt][0] = *(const uint32_t*)(sAlo + o);
                Al[mt][1] = *(const uint32_t*)(sAlo + o + 8 * SM_STRIDE);
                Al[mt][2] = *(const uint32_t*)(sAlo + o + 8);
                Al[mt][3] = *(const uint32_t*)(sAlo + o + 8 * SM_STRIDE + 8);
            }
#pragma unroll
            for (int nt = 0; nt < 4; ++nt) {
                int r = wn * 32 + nt * 8 + g;
                int o = r * SM_STRIDE + kk + kp;
                Bh[nt][0] = *(const uint32_t*)(sBhi + o);
                Bh[nt][1] = *(const uint32_t*)(sBhi + o + 8);
                Bl[nt][0] = *(const uint32_t*)(sBlo + o);
                Bl[nt][1] = *(const uint32_t*)(sBlo + o + 8);
            }
#pragma unroll
            for (int mt = 0; mt < 4; ++mt)
#pragma unroll
                for (int nt = 0; nt < 4; ++nt) {
                    MMA_BF16(acc[mt][nt], Ah[mt], Bh[nt]);
                    MMA_BF16(acc[mt][nt], Ah[mt], Bl[nt]);
                    MMA_BF16(acc[mt][nt], Al[mt], Bh[nt]);
                }
        }
        __syncthreads();
    }

    // epilogue
#pragma unroll
    for (int mt = 0; mt < 4; ++mt) {
        int row = bm + wm * 64 + mt * 16 + g;
#pragma unroll
        for (int nt = 0; nt < 4; ++nt) {
            int col = bn + wn * 32 + nt * 8 + kp;
            if (col < N) {
                float v0 = acc[mt][nt][0], v1 = acc[mt][nt][1];
                float v2 = acc[mt][nt][2], v3 = acc[mt][nt][3];
                if (EPI == 1) {
                    float b0 = bias[col], b1 = bias[col + 1];
                    v0 += b0; v1 += b1; v2 += b0; v3 += b1;
                    v0 = fmaxf(v0, 0.f) + log1pf(__expf(-fabsf(v0)));
                    v1 = fmaxf(v1, 0.f) + log1pf(__expf(-fabsf(v1)));
                    v2 = fmaxf(v2, 0.f) + log1pf(__expf(-fabsf(v2)));
                    v3 = fmaxf(v3, 0.f) + log1pf(__expf(-fabsf(v3)));
                }
                *reinterpret_cast<float2*>(&C[(size_t)row * ldc + col]) =
                    make_float2(v0, v1);
                *reinterpret_cast<float2*>(&C[(size_t)(row + 8) * ldc + col]) =
                    make_float2(v2, v3);
            }
        }
    }
}

// ---------------------------------------------------------------------------
// Depthwise causal conv (K=4, left pad 3) + bias + SiLU
// ---------------------------------------------------------------------------
__global__ void __launch_bounds__(256)
conv_silu_kernel(const float* __restrict__ xz, const float* __restrict__ w,
                 const float* __restrict__ b, float* __restrict__ h)
{
    int e = blockIdx.x * 256 + threadIdx.x;
    int l = blockIdx.y;
    float acc = b[e];
#pragma unroll
    for (int k = 0; k < KQ; ++k) {
        int ls = l - (KQ - 1) + k;
        if (ls >= 0)
            acc = fmaf(w[e * KQ + k], xz[(size_t)ls * (2 * EQ) + e], acc);
    }
    float sg = 1.f / (1.f + __expf(-acc));
    h[(size_t)l * EQ + e] = acc * sg;
}

// ---------------------------------------------------------------------------
// Selective scan: 16 e-channels x 16 n-lanes per block; serial over L.
// ---------------------------------------------------------------------------
__global__ void __launch_bounds__(256)
scan_kernel(const float* __restrict__ dt, const float* __restrict__ h,
            const float* __restrict__ ssm, const float* __restrict__ xz,
            const float* __restrict__ A_log, const float* __restrict__ Dp,
            float* __restrict__ y)
{
    int tid = threadIdx.x;
    int n   = tid & 15;
    int el  = tid >> 4;
    int e   = blockIdx.x * 16 + el;

    float a = -__expf(A_log[e * NQ + n]);
    float d = Dp[e];
    float s = 0.f;

    for (int l = 0; l < LQ; ++l) {
        float dtv = dt[(size_t)l * EQ + e];
        float hv  = h [(size_t)l * EQ + e];
        float Bv  = ssm[l * PQ + RQ + n];
        float Cv  = ssm[l * PQ + RQ + NQ + n];

        float dA = __expf(dtv * a);
        s = fmaf(s, dA, (dtv * hv) * Bv);

        float p = s * Cv;
#pragma unroll
        for (int off = 8; off; off >>= 1)
            p += __shfl_xor_sync(0xffffffffu, p, off, 16);

        if (n == 0) {
            float gte = xz[(size_t)l * (2 * EQ) + EQ + e];
            float sg  = gte / (1.f + __expf(-gte));
            y[(size_t)l * EQ + e] = (p + hv * d) * sg;
        }
    }
}

// ---------------------------------------------------------------------------
// Launcher
// ---------------------------------------------------------------------------
static inline void split_launch(const float* src, __nv_bfloat16* hi,
                                __nv_bfloat16* lo, int n)
{
    split_kernel<<<(n + 255) / 256, 256>>>(src, hi, lo, n);
}

extern "C" void kernel_launch(void* const* d_in, const int* in_sizes, int n_in,
                              void* d_out, int out_size)
{
    const float* hidden     = (const float*)d_in[0];
    const float* in_proj_w  = (const float*)d_in[1];
    const float* conv_w     = (const float*)d_in[2];
    const float* conv_b     = (const float*)d_in[3];
    const float* x_proj_w   = (const float*)d_in[4];
    const float* dt_proj_w  = (const float*)d_in[5];
    const float* dt_proj_b  = (const float*)d_in[6];
    const float* A_log      = (const float*)d_in[7];
    const float* Dp         = (const float*)d_in[8];
    const float* out_proj_w = (const float*)d_in[9];
    float* out = (float*)d_out;

    float *xz, *h, *ssmp, *dt, *y;
    cudaGetSymbolAddress((void**)&xz,   g_xz);
    cudaGetSymbolAddress((void**)&h,    g_h);
    cudaGetSymbolAddress((void**)&ssmp, g_ssm);
    cudaGetSymbolAddress((void**)&dt,   g_dt);
    cudaGetSymbolAddress((void**)&y,    g_y);

    __nv_bfloat16 *hid_hi, *hid_lo, *win_hi, *win_lo, *hb_hi, *hb_lo,
                  *wx_hi, *wx_lo, *dtr_hi, *dtr_lo, *wdt_hi, *wdt_lo,
                  *yb_hi, *yb_lo, *wout_hi, *wout_lo;
    cudaGetSymbolAddress((void**)&hid_hi,  g_hid_hi);
    cudaGetSymbolAddress((void**)&hid_lo,  g_hid_lo);
    cudaGetSymbolAddress((void**)&win_hi,  g_win_hi);
    cudaGetSymbolAddress((void**)&win_lo,  g_win_lo);
    cudaGetSymbolAddress((void**)&hb_hi,   g_hb_hi);
    cudaGetSymbolAddress((void**)&hb_lo,   g_hb_lo);
    cudaGetSymbolAddress((void**)&wx_hi,   g_wx_hi);
    cudaGetSymbolAddress((void**)&wx_lo,   g_wx_lo);
    cudaGetSymbolAddress((void**)&dtr_hi,  g_dtr_hi);
    cudaGetSymbolAddress((void**)&dtr_lo,  g_dtr_lo);
    cudaGetSymbolAddress((void**)&wdt_hi,  g_wdt_hi);
    cudaGetSymbolAddress((void**)&wdt_lo,  g_wdt_lo);
    cudaGetSymbolAddress((void**)&yb_hi,   g_yb_hi);
    cudaGetSymbolAddress((void**)&yb_lo,   g_yb_lo);
    cudaGetSymbolAddress((void**)&wout_hi, g_wout_hi);
    cudaGetSymbolAddress((void**)&wout_lo, g_wout_lo);

    cudaFuncSetAttribute(gemm_bf3<0>, cudaFuncAttributeMaxDynamicSharedMemorySize,
                         GEMM_SMEM_BYTES);
    cudaFuncSetAttribute(gemm_bf3<1>, cudaFuncAttributeMaxDynamicSharedMemorySize,
                         GEMM_SMEM_BYTES);

    // 1) split inputs for in_proj, then GEMM -> g_xz [L, 2E]
    split_launch(hidden,    hid_hi, hid_lo, LQ * HQ);
    split_launch(in_proj_w, win_hi, win_lo, 2 * EQ * HQ);
    gemm_bf3<0><<<dim3(2 * EQ / 128, LQ / 128), 256, GEMM_SMEM_BYTES>>>(
        hid_hi, hid_lo, win_hi, win_lo, xz, 2 * EQ, HQ, 2 * EQ, nullptr);

    // 2) depthwise conv + SiLU -> g_h
    conv_silu_kernel<<<dim3(EQ / 256, LQ), 256>>>(xz, conv_w, conv_b, h);

    // 3) x_proj -> g_ssm [L,160]
    split_launch(h,        hb_hi, hb_lo, LQ * EQ);
    split_launch(x_proj_w, wx_hi, wx_lo, PQ * EQ);
    gemm_bf3<0><<<dim3((PQ + 127) / 128, LQ / 128), 256, GEMM_SMEM_BYTES>>>(
        hb_hi, hb_lo, wx_hi, wx_lo, ssmp, PQ, EQ, PQ, nullptr);

    // 4) dt_proj + softplus -> g_dt [L,E]
    split_strided_kernel<<<(LQ * RQ + 255) / 256, 256>>>(
        ssmp, dtr_hi, dtr_lo, LQ, RQ, PQ);
    split_launch(dt_proj_w, wdt_hi, wdt_lo, EQ * RQ);
    gemm_bf3<1><<<dim3(EQ / 128, LQ / 128), 256, GEMM_SMEM_BYTES>>>(
        dtr_hi, dtr_lo, wdt_hi, wdt_lo, dt, EQ, RQ, EQ, dt_proj_b);

    // 5) selective scan + D skip + gate -> g_y
    scan_kernel<<<EQ / 16, 256>>>(dt, h, ssmp, xz, A_log, Dp, y);

    // 6) out_proj -> out [L,H]
    split_launch(y,          yb_hi,   yb_lo,   LQ * EQ);
    split_launch(out_proj_w, wout_hi, wout_lo, HQ * EQ);
    gemm_bf3<0><<<dim3(HQ / 128, LQ / 128), 256, GEMM_SMEM_BYTES>>>(
        yb_hi, yb_lo, wout_hi, wout_lo, out, HQ, EQ, HQ, nullptr);
}

// round 4
// speedup vs baseline: 1.6449x; 1.1661x over previous
#include <cuda_runtime.h>
#include <cuda_bf16.h>
#include <math.h>
#include <stdint.h>

// Problem constants (fixed shapes)
#define LQ 2048
#define HQ 2048
#define EQ 4096
#define NQ 16
#define KQ 4
#define RQ 128
#define PQ 160

// ---------------------------------------------------------------------------
// Scratch (device globals)
// ---------------------------------------------------------------------------
__device__ float g_xz [LQ * 2 * EQ];
__device__ float g_h  [LQ * EQ];
__device__ float g_ssm[LQ * PQ];
__device__ float g_dt [LQ * EQ];
__device__ float g_xpart[4 * LQ * PQ];

__device__ __nv_bfloat16 g_hid_hi [LQ * HQ],      g_hid_lo [LQ * HQ];
__device__ __nv_bfloat16 g_win_hi [2 * EQ * HQ],  g_win_lo [2 * EQ * HQ];
__device__ __nv_bfloat16 g_hb_hi  [LQ * EQ],      g_hb_lo  [LQ * EQ];
__device__ __nv_bfloat16 g_wx_hi  [PQ * EQ],      g_wx_lo  [PQ * EQ];
__device__ __nv_bfloat16 g_dtr_hi [LQ * RQ],      g_dtr_lo [LQ * RQ];
__device__ __nv_bfloat16 g_wdt_hi [EQ * RQ],      g_wdt_lo [EQ * RQ];
__device__ __nv_bfloat16 g_yb_hi  [LQ * EQ],      g_yb_lo  [LQ * EQ];
__device__ __nv_bfloat16 g_wout_hi[HQ * EQ],      g_wout_lo[HQ * EQ];

// ---------------------------------------------------------------------------
// mma.sync GEMM machinery (legacy tensor path; tcgen05 not available at
// this harness's PTX virtual arch)
// ---------------------------------------------------------------------------
#define MMA_BF16(c, A, B)                                                   \
    asm volatile(                                                           \
        "mma.sync.aligned.m16n8k16.row.col.f32.bf16.bf16.f32 "              \
        "{%0,%1,%2,%3}, {%4,%5,%6,%7}, {%8,%9}, {%0,%1,%2,%3};\n"           \
        : "+f"(c[0]), "+f"(c[1]), "+f"(c[2]), "+f"(c[3])                    \
        : "r"(A[0]), "r"(A[1]), "r"(A[2]), "r"(A[3]), "r"(B[0]), "r"(B[1]))

#define LDSM4(R, a)                                                         \
    asm volatile("ldmatrix.sync.aligned.m8n8.x4.shared.b16 "                \
                 "{%0,%1,%2,%3}, [%4];"                                     \
                 : "=r"((R)[0]), "=r"((R)[1]), "=r"((R)[2]), "=r"((R)[3])   \
                 : "r"(a))

#define LDSM2(R, a)                                                         \
    asm volatile("ldmatrix.sync.aligned.m8n8.x2.shared.b16 {%0,%1}, [%2];"  \
                 : "=r"((R)[0]), "=r"((R)[1]) : "r"(a))

template <int N>
__device__ __forceinline__ void cp_wait_group() {
    asm volatile("cp.async.wait_group %0;\n" :: "n"(N) : "memory");
}

__device__ __forceinline__ uint32_t smem_u32(const void* p) {
    return (uint32_t)__cvta_generic_to_shared(p);
}

// XOR swizzle for 64-byte rows (4x 16B chunks per row): chunk c of row r is
// stored at chunk (c ^ ((r>>1)&3)). Conflict-free for cp.async 16B stores and
// ldmatrix 8-row x 16B reads.
__device__ __forceinline__ uint32_t swz(int row, int c) {
    return (uint32_t)(row * 64 + ((c ^ ((row >> 1) & 3)) << 4));
}

// Per-stage SMEM: Ahi | Alo | Bhi | Blo, each 128 rows x 64B = 8KB
#define MAT_BYTES 8192
#define STG_BYTES (4 * MAT_BYTES)
#define NSTAGE 3
#define GEMM_DSMEM (NSTAGE * STG_BYTES)

// BM=128, BN=128, BK=32, 256 threads (8 warps 2x4), warp tile 64x32.
__device__ __forceinline__ void load_stage(
    uint32_t stBase, const __nv_bfloat16* Ahi, const __nv_bfloat16* Alo,
    const __nv_bfloat16* Bhi, const __nv_bfloat16* Blo,
    int bm, int bn, int N, int Kd, int k0, int tid)
{
#pragma unroll
    for (int i = 0; i < 8; ++i) {
        int idx  = i * 256 + tid;     // 0..2047
        int r512 = idx >> 2;          // 0..511
        int c    = idx & 3;           // 16B chunk within row
        int mat  = r512 >> 7;         // 0..3
        int lrow = r512 & 127;
        const __nv_bfloat16* src;
        int gRow = lrow, vb = 16;
        if (mat == 0)      { src = Ahi; gRow = bm + lrow; }
        else if (mat == 1) { src = Alo; gRow = bm + lrow; }
        else {
            gRow = bn + lrow;
            if (gRow >= N) { vb = 0; gRow = N - 1; }
            src = (mat == 2) ? Bhi : Blo;
        }
        uint32_t dst = stBase + (uint32_t)mat * MAT_BYTES + swz(lrow, c);
        const __nv_bfloat16* gp = src + (size_t)gRow * Kd + k0 + c * 8;
        asm volatile("cp.async.cg.shared.global [%0], [%1], 16, %2;\n"
                     :: "r"(dst), "l"(gp), "r"(vb));
    }
    asm volatile("cp.async.commit_group;\n" ::: "memory");
}

__device__ __forceinline__ void compute_chunk(
    uint32_t base, float acc[4][4][4], int wm, int wn, int lane)
{
    const uint32_t sAhi = base;
    const uint32_t sAlo = base + MAT_BYTES;
    const uint32_t sBhi = base + 2 * MAT_BYTES;
    const uint32_t sBlo = base + 3 * MAT_BYTES;

#pragma unroll
    for (int ks = 0; ks < 2; ++ks) {
        const int cbase = ks * 2;

        uint32_t Ah[4][4], Al[4][4];
        const int rA = lane & 15;
        const int cA = cbase + (lane >> 4);
#pragma unroll
        for (int mt = 0; mt < 4; ++mt) {
            int row = wm * 64 + mt * 16 + rA;
            uint32_t off = swz(row, cA);
            LDSM4(Ah[mt], sAhi + off);
            LDSM4(Al[mt], sAlo + off);
        }

        const int rB = lane & 7;
        const int cB = cbase + ((lane >> 3) & 1);
#pragma unroll
        for (int nt = 0; nt < 4; ++nt) {
            int row = wn * 32 + nt * 8 + rB;
            uint32_t off = swz(row, cB);
            uint32_t Bh[2], Bl[2];
            LDSM2(Bh, sBhi + off);
            LDSM2(Bl, sBlo + off);
#pragma unroll
            for (int mt = 0; mt < 4; ++mt) {
                MMA_BF16(acc[mt][nt], Ah[mt], Bh);
                MMA_BF16(acc[mt][nt], Ah[mt], Bl);
                MMA_BF16(acc[mt][nt], Al[mt], Bh);
            }
        }
    }
}

// EPI: 0 plain store, 1 softplus(x + bias[col]).
// SPLITK: gridDim.z K-partitions, each writing its own partial slab of C.
template <int EPI, bool SPLITK>
__global__ void __launch_bounds__(256, 2)
gemm_mma(const __nv_bfloat16* __restrict__ Ahi, const __nv_bfloat16* __restrict__ Alo,
         const __nv_bfloat16* __restrict__ Bhi, const __nv_bfloat16* __restrict__ Blo,
         float* __restrict__ C, int N, int Kdim, int ldc,
         const float* __restrict__ bias)
{
    extern __shared__ __align__(16) char dsm[];
    const uint32_t sbase = smem_u32(dsm);

    const int tid  = threadIdx.x;
    const int warp = tid >> 5, lane = tid & 31;
    const int wm = warp >> 2, wn = warp & 3;
    const int bm = blockIdx.y * 128, bn = blockIdx.x * 128;

    const int Kper = SPLITK ? Kdim / gridDim.z : Kdim;
    const int k00  = SPLITK ? blockIdx.z * Kper : 0;
    const int KT   = Kper >> 5;   // BK = 32

    float acc[4][4][4];
#pragma unroll
    for (int mt = 0; mt < 4; ++mt)
#pragma unroll
        for (int nt = 0; nt < 4; ++nt)
#pragma unroll
            for (int q = 0; q < 4; ++q) acc[mt][nt][q] = 0.f;

    // prologue: issue chunks 0 and 1
    load_stage(sbase, Ahi, Alo, Bhi, Blo, bm, bn, N, Kdim, k00, tid);
    if (KT > 1)
        load_stage(sbase + STG_BYTES, Ahi, Alo, Bhi, Blo, bm, bn, N, Kdim,
                   k00 + 32, tid);

    for (int kt = 0; kt < KT; ++kt) {
        if (kt < KT - 1) cp_wait_group<1>();
        else             cp_wait_group<0>();
        __syncthreads();

        if (kt + 2 < KT)
            load_stage(sbase + ((kt + 2) % NSTAGE) * STG_BYTES,
                       Ahi, Alo, Bhi, Blo, bm, bn, N, Kdim,
                       k00 + (kt + 2) * 32, tid);

        compute_chunk(sbase + (kt % NSTAGE) * STG_BYTES, acc, wm, wn, lane);
    }

    // epilogue
    float* Cout = C;
    if (SPLITK)
        Cout = C + (size_t)blockIdx.z * (size_t)(gridDim.y * 128) * ldc;

    const int g  = lane >> 2;
    const int kp = (lane & 3) << 1;
#pragma unroll
    for (int mt = 0; mt < 4; ++mt) {
        int row = bm + wm * 64 + mt * 16 + g;
#pragma unroll
        for (int nt = 0; nt < 4; ++nt) {
            int col = bn + wn * 32 + nt * 8 + kp;
            if (col < N) {
                float v0 = acc[mt][nt][0], v1 = acc[mt][nt][1];
                float v2 = acc[mt][nt][2], v3 = acc[mt][nt][3];
                if (EPI == 1) {
                    float b0 = bias[col], b1 = bias[col + 1];
                    v0 += b0; v1 += b1; v2 += b0; v3 += b1;
                    v0 = fmaxf(v0, 0.f) + log1pf(__expf(-fabsf(v0)));
                    v1 = fmaxf(v1, 0.f) + log1pf(__expf(-fabsf(v1)));
                    v2 = fmaxf(v2, 0.f) + log1pf(__expf(-fabsf(v2)));
                    v3 = fmaxf(v3, 0.f) + log1pf(__expf(-fabsf(v3)));
                }
                *reinterpret_cast<float2*>(&Cout[(size_t)row * ldc + col]) =
                    make_float2(v0, v1);
                *reinterpret_cast<float2*>(&Cout[(size_t)(row + 8) * ldc + col]) =
                    make_float2(v2, v3);
            }
        }
    }
}

// ---------------------------------------------------------------------------
// split-K reduce for x_proj
// ---------------------------------------------------------------------------
__global__ void __launch_bounds__(256)
reduce4_kernel(const float* __restrict__ part, float* __restrict__ out, int n)
{
    int i = blockIdx.x * 256 + threadIdx.x;
    if (i < n)
        out[i] = part[i] + part[n + i] + part[2 * n + i] + part[3 * n + i];
}

// ---------------------------------------------------------------------------
// fp32 -> bf16 hi/lo split (vectorized x4)
// ---------------------------------------------------------------------------
__global__ void __launch_bounds__(256)
split4_kernel(const float4* __restrict__ x, uint2* __restrict__ hi,
              uint2* __restrict__ lo, int n4)
{
    int i = blockIdx.x * 256 + threadIdx.x;
    if (i < n4) {
        float4 v = x[i];
        __nv_bfloat162 h0 = __floats2bfloat162_rn(v.x, v.y);
        __nv_bfloat162 h1 = __floats2bfloat162_rn(v.z, v.w);
        __nv_bfloat162 l0 = __floats2bfloat162_rn(v.x - __bfloat162float(h0.x),
                                                  v.y - __bfloat162float(h0.y));
        __nv_bfloat162 l1 = __floats2bfloat162_rn(v.z - __bfloat162float(h1.x),
                                                  v.w - __bfloat162float(h1.y));
        uint2 wh, wl;
        wh.x = *(uint32_t*)&h0; wh.y = *(uint32_t*)&h1;
        wl.x = *(uint32_t*)&l0; wl.y = *(uint32_t*)&l1;
        hi[i] = wh; lo[i] = wl;
    }
}

__global__ void __launch_bounds__(256)
split_strided4_kernel(const float* __restrict__ x, uint2* __restrict__ hi,
                      uint2* __restrict__ lo, int rows, int cols, int srcld)
{
    int i = blockIdx.x * 256 + threadIdx.x;
    int c4 = cols >> 2;
    if (i < rows * c4) {
        int r = i / c4, c = (i - r * c4) << 2;
        float4 v = *reinterpret_cast<const float4*>(&x[(size_t)r * srcld + c]);
        __nv_bfloat162 h0 = __floats2bfloat162_rn(v.x, v.y);
        __nv_bfloat162 h1 = __floats2bfloat162_rn(v.z, v.w);
        __nv_bfloat162 l0 = __floats2bfloat162_rn(v.x - __bfloat162float(h0.x),
                                                  v.y - __bfloat162float(h0.y));
        __nv_bfloat162 l1 = __floats2bfloat162_rn(v.z - __bfloat162float(h1.x),
                                                  v.w - __bfloat162float(h1.y));
        uint2 wh, wl;
        wh.x = *(uint32_t*)&h0; wh.y = *(uint32_t*)&h1;
        wl.x = *(uint32_t*)&l0; wl.y = *(uint32_t*)&l1;
        hi[i] = wh; lo[i] = wl;
    }
}

// ---------------------------------------------------------------------------
// Depthwise causal conv (K=4) + bias + SiLU; emits fp32 h AND bf16 hi/lo
// ---------------------------------------------------------------------------
__global__ void __launch_bounds__(256)
conv_silu_kernel(const float* __restrict__ xz, const float* __restrict__ w,
                 const float* __restrict__ b, float* __restrict__ h,
                 __nv_bfloat16* __restrict__ hhi, __nv_bfloat16* __restrict__ hlo)
{
    int e = blockIdx.x * 256 + threadIdx.x;
    int l = blockIdx.y;
    float acc = b[e];
#pragma unroll
    for (int k = 0; k < KQ; ++k) {
        int ls = l - (KQ - 1) + k;
        if (ls >= 0)
            acc = fmaf(w[e * KQ + k], xz[(size_t)ls * (2 * EQ) + e], acc);
    }
    float sg = 1.f / (1.f + __expf(-acc));
    float v = acc * sg;
    size_t o = (size_t)l * EQ + e;
    h[o] = v;
    __nv_bfloat16 vh = __float2bfloat16(v);
    hhi[o] = vh;
    hlo[o] = __float2bfloat16(v - __bfloat162float(vh));
}

// ---------------------------------------------------------------------------
// Selective scan; emits gated y directly as bf16 hi/lo
// ---------------------------------------------------------------------------
__global__ void __launch_bounds__(256)
scan_kernel(const float* __restrict__ dt, const float* __restrict__ h,
            const float* __restrict__ ssm, const float* __restrict__ xz,
            const float* __restrict__ A_log, const float* __restrict__ Dp,
            __nv_bfloat16* __restrict__ yhi, __nv_bfloat16* __restrict__ ylo)
{
    int tid = threadIdx.x;
    int n   = tid & 15;
    int el  = tid >> 4;
    int e   = blockIdx.x * 16 + el;

    float a = -__expf(A_log[e * NQ + n]);
    float d = Dp[e];
    float s = 0.f;

    for (int l = 0; l < LQ; ++l) {
        float dtv = dt[(size_t)l * EQ + e];
        float hv  = h [(size_t)l * EQ + e];
        float Bv  = ssm[l * PQ + RQ + n];
        float Cv  = ssm[l * PQ + RQ + NQ + n];

        float dA = __expf(dtv * a);
        s = fmaf(s, dA, (dtv * hv) * Bv);

        float p = s * Cv;
#pragma unroll
        for (int off = 8; off; off >>= 1)
            p += __shfl_xor_sync(0xffffffffu, p, off, 16);

        if (n == 0) {
            float g  = xz[(size_t)l * (2 * EQ) + EQ + e];
            float sg = g / (1.f + __expf(-g));
            float v  = (p + hv * d) * sg;
            size_t o = (size_t)l * EQ + e;
            __nv_bfloat16 vh = __float2bfloat16(v);
            yhi[o] = vh;
            ylo[o] = __float2bfloat16(v - __bfloat162float(vh));
        }
    }
}

// ---------------------------------------------------------------------------
// Launcher
// ---------------------------------------------------------------------------
static inline void split_launch(const float* src, __nv_bfloat16* hi,
                                __nv_bfloat16* lo, int n)
{
    split4_kernel<<<(n / 4 + 255) / 256, 256>>>(
        (const float4*)src, (uint2*)hi, (uint2*)lo, n / 4);
}

extern "C" void kernel_launch(void* const* d_in, const int* in_sizes, int n_in,
                              void* d_out, int out_size)
{
    const float* hidden     = (const float*)d_in[0];
    const float* in_proj_w  = (const float*)d_in[1];
    const float* conv_w     = (const float*)d_in[2];
    const float* conv_b     = (const float*)d_in[3];
    const float* x_proj_w   = (const float*)d_in[4];
    const float* dt_proj_w  = (const float*)d_in[5];
    const float* dt_proj_b  = (const float*)d_in[6];
    const float* A_log      = (const float*)d_in[7];
    const float* Dp         = (const float*)d_in[8];
    const float* out_proj_w = (const float*)d_in[9];
    float* out = (float*)d_out;

    float *xz, *h, *ssmp, *dt, *xpart;
    cudaGetSymbolAddress((void**)&xz,    g_xz);
    cudaGetSymbolAddress((void**)&h,     g_h);
    cudaGetSymbolAddress((void**)&ssmp,  g_ssm);
    cudaGetSymbolAddress((void**)&dt,    g_dt);
    cudaGetSymbolAddress((void**)&xpart, g_xpart);

    __nv_bfloat16 *hid_hi, *hid_lo, *win_hi, *win_lo, *hb_hi, *hb_lo,
                  *wx_hi, *wx_lo, *dtr_hi, *dtr_lo, *wdt_hi, *wdt_lo,
                  *yb_hi, *yb_lo, *wout_hi, *wout_lo;
    cudaGetSymbolAddress((void**)&hid_hi,  g_hid_hi);
    cudaGetSymbolAddress((void**)&hid_lo,  g_hid_lo);
    cudaGetSymbolAddress((void**)&win_hi,  g_win_hi);
    cudaGetSymbolAddress((void**)&win_lo,  g_win_lo);
    cudaGetSymbolAddress((void**)&hb_hi,   g_hb_hi);
    cudaGetSymbolAddress((void**)&hb_lo,   g_hb_lo);
    cudaGetSymbolAddress((void**)&wx_hi,   g_wx_hi);
    cudaGetSymbolAddress((void**)&wx_lo,   g_wx_lo);
    cudaGetSymbolAddress((void**)&dtr_hi,  g_dtr_hi);
    cudaGetSymbolAddress((void**)&dtr_lo,  g_dtr_lo);
    cudaGetSymbolAddress((void**)&wdt_hi,  g_wdt_hi);
    cudaGetSymbolAddress((void**)&wdt_lo,  g_wdt_lo);
    cudaGetSymbolAddress((void**)&yb_hi,   g_yb_hi);
    cudaGetSymbolAddress((void**)&yb_lo,   g_yb_lo);
    cudaGetSymbolAddress((void**)&wout_hi, g_wout_hi);
    cudaGetSymbolAddress((void**)&wout_lo, g_wout_lo);

    cudaFuncSetAttribute(gemm_mma<0, false>, cudaFuncAttributeMaxDynamicSharedMemorySize, GEMM_DSMEM);
    cudaFuncSetAttribute(gemm_mma<1, false>, cudaFuncAttributeMaxDynamicSharedMemorySize, GEMM_DSMEM);
    cudaFuncSetAttribute(gemm_mma<0, true>,  cudaFuncAttributeMaxDynamicSharedMemorySize, GEMM_DSMEM);

    // 1) in_proj: [L,H] @ [2E,H]^T -> g_xz [L,2E]
    split_launch(hidden,    hid_hi, hid_lo, LQ * HQ);
    split_launch(in_proj_w, win_hi, win_lo, 2 * EQ * HQ);
    gemm_mma<0, false><<<dim3(2 * EQ / 128, LQ / 128), 256, GEMM_DSMEM>>>(
        hid_hi, hid_lo, win_hi, win_lo, xz, 2 * EQ, HQ, 2 * EQ, nullptr);

    // 2) conv + SiLU -> g_h (+ bf16 split)
    conv_silu_kernel<<<dim3(EQ / 256, LQ), 256>>>(xz, conv_w, conv_b, h, hb_hi, hb_lo);

    // 3) x_proj: split-K=4 partials + reduce -> g_ssm [L,160]
    split_launch(x_proj_w, wx_hi, wx_lo, PQ * EQ);
    gemm_mma<0, true><<<dim3(2, LQ / 128, 4), 256, GEMM_DSMEM>>>(
        hb_hi, hb_lo, wx_hi, wx_lo, xpart, PQ, EQ, PQ, nullptr);
    reduce4_kernel<<<(LQ * PQ + 255) / 256, 256>>>(xpart, ssmp, LQ * PQ);

    // 4) dt_proj + softplus -> g_dt [L,E]
    split_strided4_kernel<<<(LQ * RQ / 4 + 255) / 256, 256>>>(
        ssmp, (uint2*)dtr_hi, (uint2*)dtr_lo, LQ, RQ, PQ);
    split_launch(dt_proj_w, wdt_hi, wdt_lo, EQ * RQ);
    gemm_mma<1, false><<<dim3(EQ / 128, LQ / 128), 256, GEMM_DSMEM>>>(
        dtr_hi, dtr_lo, wdt_hi, wdt_lo, dt, EQ, RQ, EQ, dt_proj_b);

    // 5) selective scan -> yb hi/lo
    scan_kernel<<<EQ / 16, 256>>>(dt, h, ssmp, xz, A_log, Dp, yb_hi, yb_lo);

    // 6) out_proj -> out [L,H]
    split_launch(out_proj_w, wout_hi, wout_lo, HQ * EQ);
    gemm_mma<0, false><<<dim3(HQ / 128, LQ / 128), 256, GEMM_DSMEM>>>(
        yb_hi, yb_lo, wout_hi, wout_lo, out, HQ, EQ, HQ, nullptr);
}

// round 5
// speedup vs baseline: 1.7990x; 1.0937x over previous
#include <cuda_runtime.h>
#include <cuda_fp16.h>
#include <math.h>
#include <stdint.h>

// Problem constants (fixed shapes)
#define LQ 2048
#define HQ 2048
#define EQ 4096
#define NQ 16
#define KQ 4
#define RQ 128
#define PQ 160

// ---------------------------------------------------------------------------
// Scratch (device globals)
// ---------------------------------------------------------------------------
__device__ float g_xz [LQ * 2 * EQ];
__device__ float g_h  [LQ * EQ];
__device__ float g_ssm[LQ * PQ];
__device__ float g_dt [LQ * EQ];
__device__ float g_xpart[4 * LQ * PQ];

// fp16 operands: activations split hi/lo, weights rounded once
__device__ __half g_hid_hi [LQ * HQ],  g_hid_lo [LQ * HQ];
__device__ __half g_win    [2 * EQ * HQ];
__device__ __half g_hb_hi  [LQ * EQ],  g_hb_lo  [LQ * EQ];
__device__ __half g_wx     [PQ * EQ];
__device__ __half g_dtr_hi [LQ * RQ],  g_dtr_lo [LQ * RQ];
__device__ __half g_wdt    [EQ * RQ];
__device__ __half g_yb_hi  [LQ * EQ],  g_yb_lo  [LQ * EQ];
__device__ __half g_wout   [HQ * EQ];

// ---------------------------------------------------------------------------
// mma.sync machinery (legacy tensor path; tcgen05 rejected at compute_103)
// ---------------------------------------------------------------------------
#define MMA_F16(c, A, B)                                                    \
    asm volatile(                                                           \
        "mma.sync.aligned.m16n8k16.row.col.f32.f16.f16.f32 "                \
        "{%0,%1,%2,%3}, {%4,%5,%6,%7}, {%8,%9}, {%0,%1,%2,%3};\n"           \
        : "+f"(c[0]), "+f"(c[1]), "+f"(c[2]), "+f"(c[3])                    \
        : "r"(A[0]), "r"(A[1]), "r"(A[2]), "r"(A[3]), "r"(B[0]), "r"(B[1]))

#define LDSM4(R, a)                                                         \
    asm volatile("ldmatrix.sync.aligned.m8n8.x4.shared.b16 "                \
                 "{%0,%1,%2,%3}, [%4];"                                     \
                 : "=r"((R)[0]), "=r"((R)[1]), "=r"((R)[2]), "=r"((R)[3])   \
                 : "r"(a))

template <int N>
__device__ __forceinline__ void cp_wait_group() {
    asm volatile("cp.async.wait_group %0;\n" :: "n"(N) : "memory");
}

__device__ __forceinline__ uint32_t smem_u32(const void* p) {
    return (uint32_t)__cvta_generic_to_shared(p);
}

// XOR swizzle for 64-byte rows (4x 16B chunks per row); conflict-free for
// cp.async 16B stores and ldmatrix 8-row x 16B reads (validated R4).
__device__ __forceinline__ uint32_t swz(int row, int c) {
    return (uint32_t)(row * 64 + ((c ^ ((row >> 1) & 3)) << 4));
}

// Per-stage SMEM: Ahi | Alo | Bw, each 128 rows x 64B = 8KB
#define MAT_BYTES 8192
#define STG_BYTES (3 * MAT_BYTES)
#define NSTAGE 3
#define GEMM_DSMEM (NSTAGE * STG_BYTES)

// BM=128, BN=128, BK=32, 256 threads (8 warps 2x4), warp tile 64x32.
__device__ __forceinline__ void load_stage(
    uint32_t stBase, const __half* Ahi, const __half* Alo, const __half* Bw,
    int bm, int bn, int N, int Kd, int k0, int tid)
{
#pragma unroll
    for (int i = 0; i < 6; ++i) {
        int idx  = i * 256 + tid;     // 0..1535
        int r512 = idx >> 2;          // 0..383
        int c    = idx & 3;           // 16B chunk within row
        int mat  = r512 >> 7;         // 0..2
        int lrow = r512 & 127;
        const __half* src;
        int gRow = lrow, vb = 16;
        if (mat == 0)      { src = Ahi; gRow = bm + lrow; }
        else if (mat == 1) { src = Alo; gRow = bm + lrow; }
        else {
            gRow = bn + lrow;
            if (gRow >= N) { vb = 0; gRow = N - 1; }
            src = Bw;
        }
        uint32_t dst = stBase + (uint32_t)mat * MAT_BYTES + swz(lrow, c);
        const __half* gp = src + (size_t)gRow * Kd + k0 + c * 8;
        asm volatile("cp.async.cg.shared.global [%0], [%1], 16, %2;\n"
                     :: "r"(dst), "l"(gp), "r"(vb));
    }
    asm volatile("cp.async.commit_group;\n" ::: "memory");
}

__device__ __forceinline__ void compute_chunk(
    uint32_t base, float acc[4][4][4], int wm, int wn, int lane)
{
    const uint32_t sAhi = base;
    const uint32_t sAlo = base + MAT_BYTES;
    const uint32_t sBw  = base + 2 * MAT_BYTES;

#pragma unroll
    for (int ks = 0; ks < 2; ++ks) {
        const int cbase = ks * 2;

        // A fragments: 16 rows x 2 chunks per LDSM4 (pattern validated R4)
        uint32_t Ah[4][4], Al[4][4];
        const int rA = lane & 15;
        const int cA = cbase + (lane >> 4);
#pragma unroll
        for (int mt = 0; mt < 4; ++mt) {
            int row = wm * 64 + mt * 16 + rA;
            uint32_t off = swz(row, cA);
            LDSM4(Ah[mt], sAhi + off);
            LDSM4(Al[mt], sAlo + off);
        }

        // B fragments: one LDSM4 covers an nt-pair (16 rows x 2 chunks):
        // matrix m = lane>>3: row = base + (m>>1)*8 + (lane&7), chunk = cbase + (m&1)
        uint32_t Bq[2][4];
        const int rB = ((lane >> 4) << 3) + (lane & 7);
        const int cB = cbase + ((lane >> 3) & 1);
#pragma unroll
        for (int p = 0; p < 2; ++p) {
            int row = wn * 32 + p * 16 + rB;
            LDSM4(Bq[p], sBw + swz(row, cB));
        }

#pragma unroll
        for (int mt = 0; mt < 4; ++mt)
#pragma unroll
            for (int p = 0; p < 2; ++p) {
                MMA_F16(acc[mt][2 * p],     Ah[mt], (&Bq[p][0]));
                MMA_F16(acc[mt][2 * p],     Al[mt], (&Bq[p][0]));
                MMA_F16(acc[mt][2 * p + 1], Ah[mt], (&Bq[p][2]));
                MMA_F16(acc[mt][2 * p + 1], Al[mt], (&Bq[p][2]));
            }
    }
}

// EPI: 0 plain store, 1 softplus(x + bias[col]).
// SPLITK: gridDim.z K-partitions, each writing its own partial slab of C.
template <int EPI, bool SPLITK>
__global__ void __launch_bounds__(256, 2)
gemm_mma(const __half* __restrict__ Ahi, const __half* __restrict__ Alo,
         const __half* __restrict__ Bw,
         float* __restrict__ C, int N, int Kdim, int ldc,
         const float* __restrict__ bias)
{
    extern __shared__ __align__(16) char dsm[];
    const uint32_t sbase = smem_u32(dsm);

    const int tid  = threadIdx.x;
    const int warp = tid >> 5, lane = tid & 31;
    const int wm = warp >> 2, wn = warp & 3;
    const int bm = blockIdx.y * 128, bn = blockIdx.x * 128;

    const int Kper = SPLITK ? Kdim / gridDim.z : Kdim;
    const int k00  = SPLITK ? blockIdx.z * Kper : 0;
    const int KT   = Kper >> 5;   // BK = 32

    float acc[4][4][4];
#pragma unroll
    for (int mt = 0; mt < 4; ++mt)
#pragma unroll
        for (int nt = 0; nt < 4; ++nt)
#pragma unroll
            for (int q = 0; q < 4; ++q) acc[mt][nt][q] = 0.f;

    load_stage(sbase, Ahi, Alo, Bw, bm, bn, N, Kdim, k00, tid);
    if (KT > 1)
        load_stage(sbase + STG_BYTES, Ahi, Alo, Bw, bm, bn, N, Kdim, k00 + 32, tid);

    for (int kt = 0; kt < KT; ++kt) {
        if (kt < KT - 1) cp_wait_group<1>();
        else             cp_wait_group<0>();
        __syncthreads();

        if (kt + 2 < KT)
            load_stage(sbase + ((kt + 2) % NSTAGE) * STG_BYTES,
                       Ahi, Alo, Bw, bm, bn, N, Kdim, k00 + (kt + 2) * 32, tid);

        compute_chunk(sbase + (kt % NSTAGE) * STG_BYTES, acc, wm, wn, lane);
    }

    float* Cout = C;
    if (SPLITK)
        Cout = C + (size_t)blockIdx.z * (size_t)(gridDim.y * 128) * ldc;

    const int g  = lane >> 2;
    const int kp = (lane & 3) << 1;
#pragma unroll
    for (int mt = 0; mt < 4; ++mt) {
        int row = bm + wm * 64 + mt * 16 + g;
#pragma unroll
        for (int nt = 0; nt < 4; ++nt) {
            int col = bn + wn * 32 + nt * 8 + kp;
            if (col < N) {
                float v0 = acc[mt][nt][0], v1 = acc[mt][nt][1];
                float v2 = acc[mt][nt][2], v3 = acc[mt][nt][3];
                if (EPI == 1) {
                    float b0 = bias[col], b1 = bias[col + 1];
                    v0 += b0; v1 += b1; v2 += b0; v3 += b1;
                    v0 = fmaxf(v0, 0.f) + log1pf(__expf(-fabsf(v0)));
                    v1 = fmaxf(v1, 0.f) + log1pf(__expf(-fabsf(v1)));
                    v2 = fmaxf(v2, 0.f) + log1pf(__expf(-fabsf(v2)));
                    v3 = fmaxf(v3, 0.f) + log1pf(__expf(-fabsf(v3)));
                }
                *reinterpret_cast<float2*>(&Cout[(size_t)row * ldc + col]) =
                    make_float2(v0, v1);
                *reinterpret_cast<float2*>(&Cout[(size_t)(row + 8) * ldc + col]) =
                    make_float2(v2, v3);
            }
        }
    }
}

// ---------------------------------------------------------------------------
// split-K reduce for x_proj
// ---------------------------------------------------------------------------
__global__ void __launch_bounds__(256)
reduce4_kernel(const float* __restrict__ part, float* __restrict__ out, int n)
{
    int i = blockIdx.x * 256 + threadIdx.x;
    if (i < n)
        out[i] = part[i] + part[n + i] + part[2 * n + i] + part[3 * n + i];
}

// ---------------------------------------------------------------------------
// fp32 -> fp16 hi/lo split (activations) and plain fp16 convert (weights)
// ---------------------------------------------------------------------------
__global__ void __launch_bounds__(256)
split4_kernel(const float4* __restrict__ x, uint2* __restrict__ hi,
              uint2* __restrict__ lo, int n4)
{
    int i = blockIdx.x * 256 + threadIdx.x;
    if (i < n4) {
        float4 v = x[i];
        __half ha = __float2half_rn(v.x), hb = __float2half_rn(v.y);
        __half hc = __float2half_rn(v.z), hd = __float2half_rn(v.w);
        __half la = __float2half_rn(v.x - __half2float(ha));
        __half lb = __float2half_rn(v.y - __half2float(hb));
        __half lc = __float2half_rn(v.z - __half2float(hc));
        __half ld = __float2half_rn(v.w - __half2float(hd));
        __half2 h0 = __halves2half2(ha, hb), h1 = __halves2half2(hc, hd);
        __half2 l0 = __halves2half2(la, lb), l1 = __halves2half2(lc, ld);
        uint2 wh, wl;
        wh.x = *(uint32_t*)&h0; wh.y = *(uint32_t*)&h1;
        wl.x = *(uint32_t*)&l0; wl.y = *(uint32_t*)&l1;
        hi[i] = wh; lo[i] = wl;
    }
}

__global__ void __launch_bounds__(256)
cvt16_kernel(const float4* __restrict__ x, uint2* __restrict__ hi, int n4)
{
    int i = blockIdx.x * 256 + threadIdx.x;
    if (i < n4) {
        float4 v = x[i];
        __half2 h0 = __halves2half2(__float2half_rn(v.x), __float2half_rn(v.y));
        __half2 h1 = __halves2half2(__float2half_rn(v.z), __float2half_rn(v.w));
        uint2 wh;
        wh.x = *(uint32_t*)&h0; wh.y = *(uint32_t*)&h1;
        hi[i] = wh;
    }
}

__global__ void __launch_bounds__(256)
split_strided4_kernel(const float* __restrict__ x, uint2* __restrict__ hi,
                      uint2* __restrict__ lo, int rows, int cols, int srcld)
{
    int i = blockIdx.x * 256 + threadIdx.x;
    int c4 = cols >> 2;
    if (i < rows * c4) {
        int r = i / c4, c = (i - r * c4) << 2;
        float4 v = *reinterpret_cast<const float4*>(&x[(size_t)r * srcld + c]);
        __half ha = __float2half_rn(v.x), hb = __float2half_rn(v.y);
        __half hc = __float2half_rn(v.z), hd = __float2half_rn(v.w);
        __half la = __float2half_rn(v.x - __half2float(ha));
        __half lb = __float2half_rn(v.y - __half2float(hb));
        __half lc = __float2half_rn(v.z - __half2float(hc));
        __half ld = __float2half_rn(v.w - __half2float(hd));
        __half2 h0 = __halves2half2(ha, hb), h1 = __halves2half2(hc, hd);
        __half2 l0 = __halves2half2(la, lb), l1 = __halves2half2(lc, ld);
        uint2 wh, wl;
        wh.x = *(uint32_t*)&h0; wh.y = *(uint32_t*)&h1;
        wl.x = *(uint32_t*)&l0; wl.y = *(uint32_t*)&l1;
        hi[i] = wh; lo[i] = wl;
    }
}

// ---------------------------------------------------------------------------
// Depthwise causal conv (K=4) + bias + SiLU; emits fp32 h AND fp16 hi/lo
// ---------------------------------------------------------------------------
__global__ void __launch_bounds__(256)
conv_silu_kernel(const float* __restrict__ xz, const float* __restrict__ w,
                 const float* __restrict__ b, float* __restrict__ h,
                 __half* __restrict__ hhi, __half* __restrict__ hlo)
{
    int e = blockIdx.x * 256 + threadIdx.x;
    int l = blockIdx.y;
    float acc = b[e];
#pragma unroll
    for (int k = 0; k < KQ; ++k) {
        int ls = l - (KQ - 1) + k;
        if (ls >= 0)
            acc = fmaf(w[e * KQ + k], xz[(size_t)ls * (2 * EQ) + e], acc);
    }
    float sg = 1.f / (1.f + __expf(-acc));
    float v = acc * sg;
    size_t o = (size_t)l * EQ + e;
    h[o] = v;
    __half vh = __float2half_rn(v);
    hhi[o] = vh;
    hlo[o] = __float2half_rn(v - __half2float(vh));
}

// ---------------------------------------------------------------------------
// Selective scan; emits gated y directly as fp16 hi/lo
// ---------------------------------------------------------------------------
__global__ void __launch_bounds__(256)
scan_kernel(const float* __restrict__ dt, const float* __restrict__ h,
            const float* __restrict__ ssm, const float* __restrict__ xz,
            const float* __restrict__ A_log, const float* __restrict__ Dp,
            __half* __restrict__ yhi, __half* __restrict__ ylo)
{
    int tid = threadIdx.x;
    int n   = tid & 15;
    int el  = tid >> 4;
    int e   = blockIdx.x * 16 + el;

    float a = -__expf(A_log[e * NQ + n]);
    float d = Dp[e];
    float s = 0.f;

    for (int l = 0; l < LQ; ++l) {
        float dtv = dt[(size_t)l * EQ + e];
        float hv  = h [(size_t)l * EQ + e];
        float Bv  = ssm[l * PQ + RQ + n];
        float Cv  = ssm[l * PQ + RQ + NQ + n];

        float dA = __expf(dtv * a);
        s = fmaf(s, dA, (dtv * hv) * Bv);

        float p = s * Cv;
#pragma unroll
        for (int off = 8; off; off >>= 1)
            p += __shfl_xor_sync(0xffffffffu, p, off, 16);

        if (n == 0) {
            float g  = xz[(size_t)l * (2 * EQ) + EQ + e];
            float sg = g / (1.f + __expf(-g));
            float v  = (p + hv * d) * sg;
            size_t o = (size_t)l * EQ + e;
            __half vh = __float2half_rn(v);
            yhi[o] = vh;
            ylo[o] = __float2half_rn(v - __half2float(vh));
        }
    }
}

// ---------------------------------------------------------------------------
// Launcher
// ---------------------------------------------------------------------------
static inline void split_launch(const float* src, __half* hi, __half* lo, int n)
{
    split4_kernel<<<(n / 4 + 255) / 256, 256>>>(
        (const float4*)src, (uint2*)hi, (uint2*)lo, n / 4);
}
static inline void cvt_launch(const float* src, __half* hi, int n)
{
    cvt16_kernel<<<(n / 4 + 255) / 256, 256>>>(
        (const float4*)src, (uint2*)hi, n / 4);
}

extern "C" void kernel_launch(void* const* d_in, const int* in_sizes, int n_in,
                              void* d_out, int out_size)
{
    const float* hidden     = (const float*)d_in[0];
    const float* in_proj_w  = (const float*)d_in[1];
    const float* conv_w     = (const float*)d_in[2];
    const float* conv_b     = (const float*)d_in[3];
    const float* x_proj_w   = (const float*)d_in[4];
    const float* dt_proj_w  = (const float*)d_in[5];
    const float* dt_proj_b  = (const float*)d_in[6];
    const float* A_log      = (const float*)d_in[7];
    const float* Dp         = (const float*)d_in[8];
    const float* out_proj_w = (const float*)d_in[9];
    float* out = (float*)d_out;

    float *xz, *h, *ssmp, *dt, *xpart;
    cudaGetSymbolAddress((void**)&xz,    g_xz);
    cudaGetSymbolAddress((void**)&h,     g_h);
    cudaGetSymbolAddress((void**)&ssmp,  g_ssm);
    cudaGetSymbolAddress((void**)&dt,    g_dt);
    cudaGetSymbolAddress((void**)&xpart, g_xpart);

    __half *hid_hi, *hid_lo, *win, *hb_hi, *hb_lo, *wx,
           *dtr_hi, *dtr_lo, *wdt, *yb_hi, *yb_lo, *wout;
    cudaGetSymbolAddress((void**)&hid_hi, g_hid_hi);
    cudaGetSymbolAddress((void**)&hid_lo, g_hid_lo);
    cudaGetSymbolAddress((void**)&win,    g_win);
    cudaGetSymbolAddress((void**)&hb_hi,  g_hb_hi);
    cudaGetSymbolAddress((void**)&hb_lo,  g_hb_lo);
    cudaGetSymbolAddress((void**)&wx,     g_wx);
    cudaGetSymbolAddress((void**)&dtr_hi, g_dtr_hi);
    cudaGetSymbolAddress((void**)&dtr_lo, g_dtr_lo);
    cudaGetSymbolAddress((void**)&wdt,    g_wdt);
    cudaGetSymbolAddress((void**)&yb_hi,  g_yb_hi);
    cudaGetSymbolAddress((void**)&yb_lo,  g_yb_lo);
    cudaGetSymbolAddress((void**)&wout,   g_wout);

    cudaFuncSetAttribute(gemm_mma<0, false>, cudaFuncAttributeMaxDynamicSharedMemorySize, GEMM_DSMEM);
    cudaFuncSetAttribute(gemm_mma<1, false>, cudaFuncAttributeMaxDynamicSharedMemorySize, GEMM_DSMEM);
    cudaFuncSetAttribute(gemm_mma<0, true>,  cudaFuncAttributeMaxDynamicSharedMemorySize, GEMM_DSMEM);

    // 1) in_proj: [L,H] @ [2E,H]^T -> g_xz [L,2E]
    split_launch(hidden, hid_hi, hid_lo, LQ * HQ);
    cvt_launch(in_proj_w, win, 2 * EQ * HQ);
    gemm_mma<0, false><<<dim3(2 * EQ / 128, LQ / 128), 256, GEMM_DSMEM>>>(
        hid_hi, hid_lo, win, xz, 2 * EQ, HQ, 2 * EQ, nullptr);

    // 2) conv + SiLU -> g_h (+ fp16 split)
    conv_silu_kernel<<<dim3(EQ / 256, LQ), 256>>>(xz, conv_w, conv_b, h, hb_hi, hb_lo);

    // 3) x_proj: split-K=4 partials + reduce -> g_ssm [L,160]
    cvt_launch(x_proj_w, wx, PQ * EQ);
    gemm_mma<0, true><<<dim3(2, LQ / 128, 4), 256, GEMM_DSMEM>>>(
        hb_hi, hb_lo, wx, xpart, PQ, EQ, PQ, nullptr);
    reduce4_kernel<<<(LQ * PQ + 255) / 256, 256>>>(xpart, ssmp, LQ * PQ);

    // 4) dt_proj + softplus -> g_dt [L,E]
    split_strided4_kernel<<<(LQ * RQ / 4 + 255) / 256, 256>>>(
        ssmp, (uint2*)dtr_hi, (uint2*)dtr_lo, LQ, RQ, PQ);
    cvt_launch(dt_proj_w, wdt, EQ * RQ);
    gemm_mma<1, false><<<dim3(EQ / 128, LQ / 128), 256, GEMM_DSMEM>>>(
        dtr_hi, dtr_lo, wdt, dt, EQ, RQ, EQ, dt_proj_b);

    // 5) selective scan -> yb hi/lo
    scan_kernel<<<EQ / 16, 256>>>(dt, h, ssmp, xz, A_log, Dp, yb_hi, yb_lo);

    // 6) out_proj -> out [L,H]
    cvt_launch(out_proj_w, wout, HQ * EQ);
    gemm_mma<0, false><<<dim3(HQ / 128, LQ / 128), 256, GEMM_DSMEM>>>(
        yb_hi, yb_lo, wout, out, HQ, EQ, HQ, nullptr);
}

// round 6
// speedup vs baseline: 2.0199x; 1.1228x over previous
#include <cuda_runtime.h>
#include <cuda_fp16.h>
#include <math.h>
#include <stdint.h>

// Problem constants (fixed shapes)
#define LQ 2048
#define HQ 2048
#define EQ 4096
#define NQ 16
#define KQ 4
#define RQ 128
#define PQ 160

// ---------------------------------------------------------------------------
// Scratch (device globals)
// ---------------------------------------------------------------------------
__device__ float g_xz [LQ * 2 * EQ];
__device__ float g_h  [LQ * EQ];
__device__ float g_ssm[LQ * PQ];
__device__ float g_dt [LQ * EQ];
__device__ float g_xpart[4 * LQ * PQ];

// fp16 operands (1-pass: both sides rounded once)
__device__ __half g_hid [LQ * HQ];
__device__ __half g_win [2 * EQ * HQ];
__device__ __half g_hb  [LQ * EQ];
__device__ __half g_wx  [PQ * EQ];
__device__ __half g_dtr [LQ * RQ];
__device__ __half g_wdt [EQ * RQ];
__device__ __half g_yb  [LQ * EQ];
__device__ __half g_wout[HQ * EQ];

// ---------------------------------------------------------------------------
// mma.sync machinery (legacy tensor path; tcgen05 rejected at compute_103)
// ---------------------------------------------------------------------------
#define MMA_F16(c, A, B)                                                    \
    asm volatile(                                                           \
        "mma.sync.aligned.m16n8k16.row.col.f32.f16.f16.f32 "                \
        "{%0,%1,%2,%3}, {%4,%5,%6,%7}, {%8,%9}, {%0,%1,%2,%3};\n"           \
        : "+f"(c[0]), "+f"(c[1]), "+f"(c[2]), "+f"(c[3])                    \
        : "r"(A[0]), "r"(A[1]), "r"(A[2]), "r"(A[3]), "r"(B[0]), "r"(B[1]))

#define LDSM4(R, a)                                                         \
    asm volatile("ldmatrix.sync.aligned.m8n8.x4.shared.b16 "                \
                 "{%0,%1,%2,%3}, [%4];"                                     \
                 : "=r"((R)[0]), "=r"((R)[1]), "=r"((R)[2]), "=r"((R)[3])   \
                 : "r"(a))

template <int N>
__device__ __forceinline__ void cp_wait_group() {
    asm volatile("cp.async.wait_group %0;\n" :: "n"(N) : "memory");
}

__device__ __forceinline__ uint32_t smem_u32(const void* p) {
    return (uint32_t)__cvta_generic_to_shared(p);
}

// XOR swizzle for 64-byte rows (4x 16B chunks); conflict-free for cp.async
// 16B stores and ldmatrix reads (validated R4/R5).
__device__ __forceinline__ uint32_t swz(int row, int c) {
    return (uint32_t)(row * 64 + ((c ^ ((row >> 1) & 3)) << 4));
}

// Per-stage SMEM: A | B, each 128 rows x 64B = 8KB
#define MAT_BYTES 8192
#define STG_BYTES (2 * MAT_BYTES)
#define NSTAGE 4
#define GEMM_DSMEM (NSTAGE * STG_BYTES)

// BM=128, BN=128, BK=32, 256 threads (8 warps 2x4), warp tile 64x32.
__device__ __forceinline__ void load_stage(
    uint32_t stBase, const __half* A, const __half* Bw,
    int bm, int bn, int N, int Kd, int k0, int tid)
{
#pragma unroll
    for (int i = 0; i < 4; ++i) {
        int idx  = i * 256 + tid;     // 0..1023
        int r512 = idx >> 2;          // 0..255
        int c    = idx & 3;           // 16B chunk within row
        int mat  = r512 >> 7;         // 0..1
        int lrow = r512 & 127;
        const __half* src;
        int gRow = lrow, vb = 16;
        if (mat == 0) { src = A; gRow = bm + lrow; }
        else {
            gRow = bn + lrow;
            if (gRow >= N) { vb = 0; gRow = N - 1; }
            src = Bw;
        }
        uint32_t dst = stBase + (uint32_t)mat * MAT_BYTES + swz(lrow, c);
        const __half* gp = src + (size_t)gRow * Kd + k0 + c * 8;
        asm volatile("cp.async.cg.shared.global [%0], [%1], 16, %2;\n"
                     :: "r"(dst), "l"(gp), "r"(vb));
    }
    asm volatile("cp.async.commit_group;\n" ::: "memory");
}

__device__ __forceinline__ void compute_chunk(
    uint32_t base, float acc[4][4][4], int wm, int wn, int lane)
{
    const uint32_t sA = base;
    const uint32_t sB = base + MAT_BYTES;

#pragma unroll
    for (int ks = 0; ks < 2; ++ks) {
        const int cbase = ks * 2;

        uint32_t Ah[4][4];
        const int rA = lane & 15;
        const int cA = cbase + (lane >> 4);
#pragma unroll
        for (int mt = 0; mt < 4; ++mt)
            LDSM4(Ah[mt], sA + swz(wm * 64 + mt * 16 + rA, cA));

        uint32_t Bq[2][4];
        const int rB = ((lane >> 4) << 3) + (lane & 7);
        const int cB = cbase + ((lane >> 3) & 1);
#pragma unroll
        for (int p = 0; p < 2; ++p)
            LDSM4(Bq[p], sB + swz(wn * 32 + p * 16 + rB, cB));

#pragma unroll
        for (int mt = 0; mt < 4; ++mt)
#pragma unroll
            for (int p = 0; p < 2; ++p) {
                MMA_F16(acc[mt][2 * p],     Ah[mt], (&Bq[p][0]));
                MMA_F16(acc[mt][2 * p + 1], Ah[mt], (&Bq[p][2]));
            }
    }
}

// EPI: 0 plain store, 1 softplus(x + bias[col]).
// SPLITK: gridDim.z K-partitions, each writing its own partial slab of C.
template <int EPI, bool SPLITK>
__global__ void __launch_bounds__(256, 2)
gemm_mma(const __half* __restrict__ A, const __half* __restrict__ Bw,
         float* __restrict__ C, int N, int Kdim, int ldc,
         const float* __restrict__ bias)
{
    extern __shared__ __align__(16) char dsm[];
    const uint32_t sbase = smem_u32(dsm);

    const int tid  = threadIdx.x;
    const int warp = tid >> 5, lane = tid & 31;
    const int wm = warp >> 2, wn = warp & 3;
    const int bm = blockIdx.y * 128, bn = blockIdx.x * 128;

    const int Kper = SPLITK ? Kdim / gridDim.z : Kdim;
    const int k00  = SPLITK ? blockIdx.z * Kper : 0;
    const int KT   = Kper >> 5;   // BK = 32

    float acc[4][4][4];
#pragma unroll
    for (int mt = 0; mt < 4; ++mt)
#pragma unroll
        for (int nt = 0; nt < 4; ++nt)
#pragma unroll
            for (int q = 0; q < 4; ++q) acc[mt][nt][q] = 0.f;

    // prologue: depth-3 prefetch
    load_stage(sbase, A, Bw, bm, bn, N, Kdim, k00, tid);
    if (KT > 1) load_stage(sbase + STG_BYTES, A, Bw, bm, bn, N, Kdim, k00 + 32, tid);
    if (KT > 2) load_stage(sbase + 2 * STG_BYTES, A, Bw, bm, bn, N, Kdim, k00 + 64, tid);

    for (int kt = 0; kt < KT; ++kt) {
        if (kt + 2 < KT)      cp_wait_group<2>();
        else if (kt + 1 < KT) cp_wait_group<1>();
        else                  cp_wait_group<0>();
        __syncthreads();

        if (kt + 3 < KT)
            load_stage(sbase + ((kt + 3) % NSTAGE) * STG_BYTES,
                       A, Bw, bm, bn, N, Kdim, k00 + (kt + 3) * 32, tid);

        compute_chunk(sbase + (kt % NSTAGE) * STG_BYTES, acc, wm, wn, lane);
    }

    float* Cout = C;
    if (SPLITK)
        Cout = C + (size_t)blockIdx.z * (size_t)(gridDim.y * 128) * ldc;

    const int g  = lane >> 2;
    const int kp = (lane & 3) << 1;
#pragma unroll
    for (int mt = 0; mt < 4; ++mt) {
        int row = bm + wm * 64 + mt * 16 + g;
#pragma unroll
        for (int nt = 0; nt < 4; ++nt) {
            int col = bn + wn * 32 + nt * 8 + kp;
            if (col < N) {
                float v0 = acc[mt][nt][0], v1 = acc[mt][nt][1];
                float v2 = acc[mt][nt][2], v3 = acc[mt][nt][3];
                if (EPI == 1) {
                    float b0 = bias[col], b1 = bias[col + 1];
                    v0 += b0; v1 += b1; v2 += b0; v3 += b1;
                    v0 = fmaxf(v0, 0.f) + log1pf(__expf(-fabsf(v0)));
                    v1 = fmaxf(v1, 0.f) + log1pf(__expf(-fabsf(v1)));
                    v2 = fmaxf(v2, 0.f) + log1pf(__expf(-fabsf(v2)));
                    v3 = fmaxf(v3, 0.f) + log1pf(__expf(-fabsf(v3)));
                }
                *reinterpret_cast<float2*>(&Cout[(size_t)row * ldc + col]) =
                    make_float2(v0, v1);
                *reinterpret_cast<float2*>(&Cout[(size_t)(row + 8) * ldc + col]) =
                    make_float2(v2, v3);
            }
        }
    }
}

// ---------------------------------------------------------------------------
// split-K reduce for x_proj
// ---------------------------------------------------------------------------
__global__ void __launch_bounds__(256)
reduce4_kernel(const float* __restrict__ part, float* __restrict__ out, int n)
{
    int i = blockIdx.x * 256 + threadIdx.x;
    if (i < n)
        out[i] = part[i] + part[n + i] + part[2 * n + i] + part[3 * n + i];
}

// ---------------------------------------------------------------------------
// fp32 -> fp16 convert (vectorized x4); strided variant for dt rows
// ---------------------------------------------------------------------------
__global__ void __launch_bounds__(256)
cvt16_kernel(const float4* __restrict__ x, uint2* __restrict__ o, int n4)
{
    int i = blockIdx.x * 256 + threadIdx.x;
    if (i < n4) {
        float4 v = x[i];
        __half2 h0 = __halves2half2(__float2half_rn(v.x), __float2half_rn(v.y));
        __half2 h1 = __halves2half2(__float2half_rn(v.z), __float2half_rn(v.w));
        uint2 w;
        w.x = *(uint32_t*)&h0; w.y = *(uint32_t*)&h1;
        o[i] = w;
    }
}

__global__ void __launch_bounds__(256)
cvt_strided4_kernel(const float* __restrict__ x, uint2* __restrict__ o,
                    int rows, int cols, int srcld)
{
    int i = blockIdx.x * 256 + threadIdx.x;
    int c4 = cols >> 2;
    if (i < rows * c4) {
        int r = i / c4, c = (i - r * c4) << 2;
        float4 v = *reinterpret_cast<const float4*>(&x[(size_t)r * srcld + c]);
        __half2 h0 = __halves2half2(__float2half_rn(v.x), __float2half_rn(v.y));
        __half2 h1 = __halves2half2(__float2half_rn(v.z), __float2half_rn(v.w));
        uint2 w;
        w.x = *(uint32_t*)&h0; w.y = *(uint32_t*)&h1;
        o[i] = w;
    }
}

// ---------------------------------------------------------------------------
// Depthwise causal conv (K=4) + bias + SiLU; emits fp32 h AND fp16 copy
// ---------------------------------------------------------------------------
__global__ void __launch_bounds__(256)
conv_silu_kernel(const float* __restrict__ xz, const float* __restrict__ w,
                 const float* __restrict__ b, float* __restrict__ h,
                 __half* __restrict__ hh)
{
    int e = blockIdx.x * 256 + threadIdx.x;
    int l = blockIdx.y;
    float acc = b[e];
#pragma unroll
    for (int k = 0; k < KQ; ++k) {
        int ls = l - (KQ - 1) + k;
        if (ls >= 0)
            acc = fmaf(w[e * KQ + k], xz[(size_t)ls * (2 * EQ) + e], acc);
    }
    float sg = 1.f / (1.f + __expf(-acc));
    float v = acc * sg;
    size_t o = (size_t)l * EQ + e;
    h[o] = v;
    hh[o] = __float2half_rn(v);
}

// ---------------------------------------------------------------------------
// Selective scan; emits gated y directly as fp16
// ---------------------------------------------------------------------------
__global__ void __launch_bounds__(256)
scan_kernel(const float* __restrict__ dt, const float* __restrict__ h,
            const float* __restrict__ ssm, const float* __restrict__ xz,
            const float* __restrict__ A_log, const float* __restrict__ Dp,
            __half* __restrict__ y)
{
    int tid = threadIdx.x;
    int n   = tid & 15;
    int el  = tid >> 4;
    int e   = blockIdx.x * 16 + el;

    float a = -__expf(A_log[e * NQ + n]);
    float d = Dp[e];
    float s = 0.f;

    for (int l = 0; l < LQ; ++l) {
        float dtv = dt[(size_t)l * EQ + e];
        float hv  = h [(size_t)l * EQ + e];
        float Bv  = ssm[l * PQ + RQ + n];
        float Cv  = ssm[l * PQ + RQ + NQ + n];

        float dA = __expf(dtv * a);
        s = fmaf(s, dA, (dtv * hv) * Bv);

        float p = s * Cv;
#pragma unroll
        for (int off = 8; off; off >>= 1)
            p += __shfl_xor_sync(0xffffffffu, p, off, 16);

        if (n == 0) {
            float g  = xz[(size_t)l * (2 * EQ) + EQ + e];
            float sg = g / (1.f + __expf(-g));
            float v  = (p + hv * d) * sg;
            y[(size_t)l * EQ + e] = __float2half_rn(v);
        }
    }
}

// ---------------------------------------------------------------------------
// Launcher
// ---------------------------------------------------------------------------
static inline void cvt_launch(const float* src, __half* dst, int n)
{
    cvt16_kernel<<<(n / 4 + 255) / 256, 256>>>(
        (const float4*)src, (uint2*)dst, n / 4);
}

extern "C" void kernel_launch(void* const* d_in, const int* in_sizes, int n_in,
                              void* d_out, int out_size)
{
    const float* hidden     = (const float*)d_in[0];
    const float* in_proj_w  = (const float*)d_in[1];
    const float* conv_w     = (const float*)d_in[2];
    const float* conv_b     = (const float*)d_in[3];
    const float* x_proj_w   = (const float*)d_in[4];
    const float* dt_proj_w  = (const float*)d_in[5];
    const float* dt_proj_b  = (const float*)d_in[6];
    const float* A_log      = (const float*)d_in[7];
    const float* Dp         = (const float*)d_in[8];
    const float* out_proj_w = (const float*)d_in[9];
    float* out = (float*)d_out;

    float *xz, *h, *ssmp, *dt, *xpart;
    cudaGetSymbolAddress((void**)&xz,    g_xz);
    cudaGetSymbolAddress((void**)&h,     g_h);
    cudaGetSymbolAddress((void**)&ssmp,  g_ssm);
    cudaGetSymbolAddress((void**)&dt,    g_dt);
    cudaGetSymbolAddress((void**)&xpart, g_xpart);

    __half *hid, *win, *hb, *wx, *dtr, *wdt, *yb, *wout;
    cudaGetSymbolAddress((void**)&hid,  g_hid);
    cudaGetSymbolAddress((void**)&win,  g_win);
    cudaGetSymbolAddress((void**)&hb,   g_hb);
    cudaGetSymbolAddress((void**)&wx,   g_wx);
    cudaGetSymbolAddress((void**)&dtr,  g_dtr);
    cudaGetSymbolAddress((void**)&wdt,  g_wdt);
    cudaGetSymbolAddress((void**)&yb,   g_yb);
    cudaGetSymbolAddress((void**)&wout, g_wout);

    cudaFuncSetAttribute(gemm_mma<0, false>, cudaFuncAttributeMaxDynamicSharedMemorySize, GEMM_DSMEM);
    cudaFuncSetAttribute(gemm_mma<1, false>, cudaFuncAttributeMaxDynamicSharedMemorySize, GEMM_DSMEM);
    cudaFuncSetAttribute(gemm_mma<0, true>,  cudaFuncAttributeMaxDynamicSharedMemorySize, GEMM_DSMEM);

    // 1) in_proj: [L,H] @ [2E,H]^T -> g_xz [L,2E]
    cvt_launch(hidden, hid, LQ * HQ);
    cvt_launch(in_proj_w, win, 2 * EQ * HQ);
    gemm_mma<0, false><<<dim3(2 * EQ / 128, LQ / 128), 256, GEMM_DSMEM>>>(
        hid, win, xz, 2 * EQ, HQ, 2 * EQ, nullptr);

    // 2) conv + SiLU -> g_h (+ fp16 copy)
    conv_silu_kernel<<<dim3(EQ / 256, LQ), 256>>>(xz, conv_w, conv_b, h, hb);

    // 3) x_proj: split-K=4 partials + reduce -> g_ssm [L,160]
    cvt_launch(x_proj_w, wx, PQ * EQ);
    gemm_mma<0, true><<<dim3(2, LQ / 128, 4), 256, GEMM_DSMEM>>>(
        hb, wx, xpart, PQ, EQ, PQ, nullptr);
    reduce4_kernel<<<(LQ * PQ + 255) / 256, 256>>>(xpart, ssmp, LQ * PQ);

    // 4) dt_proj + softplus -> g_dt [L,E]
    cvt_strided4_kernel<<<(LQ * RQ / 4 + 255) / 256, 256>>>(
        ssmp, (uint2*)dtr, LQ, RQ, PQ);
    cvt_launch(dt_proj_w, wdt, EQ * RQ);
    gemm_mma<1, false><<<dim3(EQ / 128, LQ / 128), 256, GEMM_DSMEM>>>(
        dtr, wdt, dt, EQ, RQ, EQ, dt_proj_b);

    // 5) selective scan -> yb (fp16)
    scan_kernel<<<EQ / 16, 256>>>(dt, h, ssmp, xz, A_log, Dp, yb);

    // 6) out_proj -> out [L,H]
    cvt_launch(out_proj_w, wout, HQ * EQ);
    gemm_mma<0, false><<<dim3(HQ / 128, LQ / 128), 256, GEMM_DSMEM>>>(
        yb, wout, out, HQ, EQ, HQ, nullptr);
}

// round 7
// speedup vs baseline: 2.0547x; 1.0172x over previous
#include <cuda_runtime.h>
#include <cuda.h>
#include <cuda_fp16.h>
#include <math.h>
#include <stdint.h>

// Problem constants (fixed shapes)
#define LQ 2048
#define HQ 2048
#define EQ 4096
#define NQ 16
#define KQ 4
#define RQ 128
#define PQ 160

// ---------------------------------------------------------------------------
// Scratch (device globals)
// ---------------------------------------------------------------------------
__device__ float g_xz [LQ * 2 * EQ];
__device__ float g_h  [LQ * EQ];
__device__ float g_ssm[LQ * PQ];
__device__ float g_dt [LQ * EQ];
__device__ float g_xpart[4 * LQ * PQ];

// fp16 operands (1-pass rounding; rel_err budget validated R6)
__device__ __align__(256) __half g_hid [LQ * HQ];
__device__ __align__(256) __half g_win [2 * EQ * HQ];
__device__ __align__(256) __half g_hb  [LQ * EQ];
__device__ __align__(256) __half g_wx  [PQ * EQ];
__device__ __align__(256) __half g_dtr [LQ * RQ];
__device__ __align__(256) __half g_wdt [EQ * RQ];
__device__ __align__(256) __half g_yb  [LQ * EQ];
__device__ __align__(256) __half g_wout[HQ * EQ];

// ---------------------------------------------------------------------------
// PTX helpers
// ---------------------------------------------------------------------------
#define MMA_F16(c, A, B)                                                    \
    asm volatile(                                                           \
        "mma.sync.aligned.m16n8k16.row.col.f32.f16.f16.f32 "                \
        "{%0,%1,%2,%3}, {%4,%5,%6,%7}, {%8,%9}, {%0,%1,%2,%3};\n"           \
        : "+f"(c[0]), "+f"(c[1]), "+f"(c[2]), "+f"(c[3])                    \
        : "r"(A[0]), "r"(A[1]), "r"(A[2]), "r"(A[3]), "r"(B[0]), "r"(B[1]))

#define LDSM4(R, a)                                                         \
    asm volatile("ldmatrix.sync.aligned.m8n8.x4.shared.b16 "                \
                 "{%0,%1,%2,%3}, [%4];"                                     \
                 : "=r"((R)[0]), "=r"((R)[1]), "=r"((R)[2]), "=r"((R)[3])   \
                 : "r"(a))

__device__ __forceinline__ uint32_t smem_u32(const void* p) {
    return (uint32_t)__cvta_generic_to_shared(p);
}
__device__ __forceinline__ void mbar_init(uint32_t a, uint32_t cnt) {
    asm volatile("mbarrier.init.shared.b64 [%0], %1;" :: "r"(a), "r"(cnt) : "memory");
}
__device__ __forceinline__ void mbar_expect_tx(uint32_t a, uint32_t bytes) {
    asm volatile("mbarrier.arrive.expect_tx.shared.b64 _, [%0], %1;"
                 :: "r"(a), "r"(bytes) : "memory");
}
__device__ __forceinline__ void mbar_wait(uint32_t a, uint32_t ph) {
    asm volatile("{\n\t.reg .pred P;\n\t"
                 "WL_%=:\n\t"
                 "mbarrier.try_wait.parity.acquire.cta.shared::cta.b64 P, [%0], %1, 0x989680;\n\t"
                 "@P bra WD_%=;\n\tbra WL_%=;\n\tWD_%=:\n\t}"
                 :: "r"(a), "r"(ph) : "memory");
}
__device__ __forceinline__ void tma_load_2d(uint32_t dst, const CUtensorMap* tm,
                                            int cx, int cy, uint32_t mbar) {
    asm volatile(
        "cp.async.bulk.tensor.2d.shared::cluster.global.tile.mbarrier::complete_tx::bytes "
        "[%0], [%1, {%2, %3}], [%4];"
        :: "r"(dst), "l"(tm), "r"(cx), "r"(cy), "r"(mbar) : "memory");
}

// ---------------------------------------------------------------------------
// TMA tensor-core GEMM: C[M,N] = epi( A[M,K] * B[N,K]^T ), fp16 in fp32 acc
// BM=128, BN=128, BK=64, 256 threads (8 warps 2x4), warp tile 64x32.
// SW128 swizzle (128B rows): logical (row, 16B-chunk c) at row*128 + ((c^(row&7))*16)
// 3 stages x 32KB, TMA producer (tid 0) + mbarrier expect_tx.
// ---------------------------------------------------------------------------
#define MAT_BYTES 16384
#define STG_BYTES (2 * MAT_BYTES)
#define NSTAGE 3
#define GEMM_DSMEM (NSTAGE * STG_BYTES + 1024)

__device__ __forceinline__ void compute_chunk(
    uint32_t base, float acc[4][4][4], int wm, int wn, int lane)
{
    const uint32_t sA = base;
    const uint32_t sB = base + MAT_BYTES;

#pragma unroll
    for (int ks = 0; ks < 4; ++ks) {
        const int cb = 2 * ks;

        uint32_t Ah[4][4];
        const int rA = lane & 15;
        const int cA = cb + (lane >> 4);
#pragma unroll
        for (int mt = 0; mt < 4; ++mt) {
            int row = wm * 64 + mt * 16 + rA;
            LDSM4(Ah[mt], sA + (uint32_t)(row * 128 + ((cA ^ (row & 7)) << 4)));
        }

        uint32_t Bq[2][4];
        const int rB = ((lane >> 4) << 3) + (lane & 7);
        const int cB = cb + ((lane >> 3) & 1);
#pragma unroll
        for (int p = 0; p < 2; ++p) {
            int row = wn * 32 + p * 16 + rB;
            LDSM4(Bq[p], sB + (uint32_t)(row * 128 + ((cB ^ (row & 7)) << 4)));
        }

#pragma unroll
        for (int mt = 0; mt < 4; ++mt)
#pragma unroll
            for (int p = 0; p < 2; ++p) {
                MMA_F16(acc[mt][2 * p],     Ah[mt], (&Bq[p][0]));
                MMA_F16(acc[mt][2 * p + 1], Ah[mt], (&Bq[p][2]));
            }
    }
}

// EPI: 0 plain store, 1 softplus(x + bias[col]).
// SPLITK: gridDim.z K-partitions, each writing its own partial slab of C.
template <int EPI, bool SPLITK>
__global__ void __launch_bounds__(256, 2)
gemm_tma(const __grid_constant__ CUtensorMap tmA,
         const __grid_constant__ CUtensorMap tmB,
         float* __restrict__ C, int N, int Kdim, int ldc,
         const float* __restrict__ bias)
{
    extern __shared__ __align__(16) char dsm[];
    __shared__ __align__(8) uint64_t s_mb[NSTAGE];

    const uint32_t sbase = (smem_u32(dsm) + 1023u) & ~1023u;
    const int tid  = threadIdx.x;
    const int warp = tid >> 5, lane = tid & 31;
    const int wm = warp >> 2, wn = warp & 3;
    const int bm = blockIdx.y * 128, bn = blockIdx.x * 128;

    const int Kper = SPLITK ? Kdim / gridDim.z : Kdim;
    const int k00  = SPLITK ? blockIdx.z * Kper : 0;
    const int KT   = Kper >> 6;   // BK = 64

    if (tid == 0) {
#pragma unroll
        for (int s = 0; s < NSTAGE; ++s) mbar_init(smem_u32(&s_mb[s]), 1);
        asm volatile("fence.proxy.async.shared::cta;" ::: "memory");
    }
    __syncthreads();

    // prologue: issue up to 3 stages
    if (tid == 0) {
#pragma unroll
        for (int s = 0; s < NSTAGE; ++s) {
            if (s < KT) {
                uint32_t mb = smem_u32(&s_mb[s]);
                mbar_expect_tx(mb, STG_BYTES);
                tma_load_2d(sbase + s * STG_BYTES,             &tmA, k00 + s * 64, bm, mb);
                tma_load_2d(sbase + s * STG_BYTES + MAT_BYTES, &tmB, k00 + s * 64, bn, mb);
            }
        }
    }

    float acc[4][4][4];
#pragma unroll
    for (int mt = 0; mt < 4; ++mt)
#pragma unroll
        for (int nt = 0; nt < 4; ++nt)
#pragma unroll
            for (int q = 0; q < 4; ++q) acc[mt][nt][q] = 0.f;

    for (int kt = 0; kt < KT; ++kt) {
        const int s  = kt % NSTAGE;
        const int ph = (kt / NSTAGE) & 1;
        mbar_wait(smem_u32(&s_mb[s]), ph);

        compute_chunk(sbase + s * STG_BYTES, acc, wm, wn, lane);

        __syncthreads();   // all warps done reading stage s
        if (tid == 0 && kt + NSTAGE < KT) {
            uint32_t mb = smem_u32(&s_mb[s]);
            mbar_expect_tx(mb, STG_BYTES);
            tma_load_2d(sbase + s * STG_BYTES,             &tmA, k00 + (kt + NSTAGE) * 64, bm, mb);
            tma_load_2d(sbase + s * STG_BYTES + MAT_BYTES, &tmB, k00 + (kt + NSTAGE) * 64, bn, mb);
        }
    }

    float* Cout = C;
    if (SPLITK)
        Cout = C + (size_t)blockIdx.z * (size_t)(gridDim.y * 128) * ldc;

    const int g  = lane >> 2;
    const int kp = (lane & 3) << 1;
#pragma unroll
    for (int mt = 0; mt < 4; ++mt) {
        int row = bm + wm * 64 + mt * 16 + g;
#pragma unroll
        for (int nt = 0; nt < 4; ++nt) {
            int col = bn + wn * 32 + nt * 8 + kp;
            if (col < N) {
                float v0 = acc[mt][nt][0], v1 = acc[mt][nt][1];
                float v2 = acc[mt][nt][2], v3 = acc[mt][nt][3];
                if (EPI == 1) {
                    float b0 = bias[col], b1 = bias[col + 1];
                    v0 += b0; v1 += b1; v2 += b0; v3 += b1;
                    v0 = fmaxf(v0, 0.f) + log1pf(__expf(-fabsf(v0)));
                    v1 = fmaxf(v1, 0.f) + log1pf(__expf(-fabsf(v1)));
                    v2 = fmaxf(v2, 0.f) + log1pf(__expf(-fabsf(v2)));
                    v3 = fmaxf(v3, 0.f) + log1pf(__expf(-fabsf(v3)));
                }
                *reinterpret_cast<float2*>(&Cout[(size_t)row * ldc + col]) =
                    make_float2(v0, v1);
                *reinterpret_cast<float2*>(&Cout[(size_t)(row + 8) * ldc + col]) =
                    make_float2(v2, v3);
            }
        }
    }
}

// ---------------------------------------------------------------------------
// split-K reduce for x_proj
// ---------------------------------------------------------------------------
__global__ void __launch_bounds__(256)
reduce4_kernel(const float* __restrict__ part, float* __restrict__ out, int n)
{
    int i = blockIdx.x * 256 + threadIdx.x;
    if (i < n)
        out[i] = part[i] + part[n + i] + part[2 * n + i] + part[3 * n + i];
}

// ---------------------------------------------------------------------------
// fp32 -> fp16 convert (vectorized x4); strided variant for dt rows
// ---------------------------------------------------------------------------
__global__ void __launch_bounds__(256)
cvt16_kernel(const float4* __restrict__ x, uint2* __restrict__ o, int n4)
{
    int i = blockIdx.x * 256 + threadIdx.x;
    if (i < n4) {
        float4 v = x[i];
        __half2 h0 = __halves2half2(__float2half_rn(v.x), __float2half_rn(v.y));
        __half2 h1 = __halves2half2(__float2half_rn(v.z), __float2half_rn(v.w));
        uint2 w;
        w.x = *(uint32_t*)&h0; w.y = *(uint32_t*)&h1;
        o[i] = w;
    }
}

__global__ void __launch_bounds__(256)
cvt_strided4_kernel(const float* __restrict__ x, uint2* __restrict__ o,
                    int rows, int cols, int srcld)
{
    int i = blockIdx.x * 256 + threadIdx.x;
    int c4 = cols >> 2;
    if (i < rows * c4) {
        int r = i / c4, c = (i - r * c4) << 2;
        float4 v = *reinterpret_cast<const float4*>(&x[(size_t)r * srcld + c]);
        __half2 h0 = __halves2half2(__float2half_rn(v.x), __float2half_rn(v.y));
        __half2 h1 = __halves2half2(__float2half_rn(v.z), __float2half_rn(v.w));
        uint2 w;
        w.x = *(uint32_t*)&h0; w.y = *(uint32_t*)&h1;
        o[i] = w;
    }
}

// ---------------------------------------------------------------------------
// Depthwise causal conv (K=4) + bias + SiLU; emits fp32 h AND fp16 copy
// ---------------------------------------------------------------------------
__global__ void __launch_bounds__(256)
conv_silu_kernel(const float* __restrict__ xz, const float* __restrict__ w,
                 const float* __restrict__ b, float* __restrict__ h,
                 __half* __restrict__ hh)
{
    int e = blockIdx.x * 256 + threadIdx.x;
    int l = blockIdx.y;
    float acc = b[e];
#pragma unroll
    for (int k = 0; k < KQ; ++k) {
        int ls = l - (KQ - 1) + k;
        if (ls >= 0)
            acc = fmaf(w[e * KQ + k], xz[(size_t)ls * (2 * EQ) + e], acc);
    }
    float sg = 1.f / (1.f + __expf(-acc));
    float v = acc * sg;
    size_t o = (size_t)l * EQ + e;
    h[o] = v;
    hh[o] = __float2half_rn(v);
}

// ---------------------------------------------------------------------------
// Selective scan; emits gated y directly as fp16
// ---------------------------------------------------------------------------
__global__ void __launch_bounds__(256)
scan_kernel(const float* __restrict__ dt, const float* __restrict__ h,
            const float* __restrict__ ssm, const float* __restrict__ xz,
            const float* __restrict__ A_log, const float* __restrict__ Dp,
            __half* __restrict__ y)
{
    int tid = threadIdx.x;
    int n   = tid & 15;
    int el  = tid >> 4;
    int e   = blockIdx.x * 16 + el;

    float a = -__expf(A_log[e * NQ + n]);
    float d = Dp[e];
    float s = 0.f;

    for (int l = 0; l < LQ; ++l) {
        float dtv = dt[(size_t)l * EQ + e];
        float hv  = h [(size_t)l * EQ + e];
        float Bv  = ssm[l * PQ + RQ + n];
        float Cv  = ssm[l * PQ + RQ + NQ + n];

        float dA = __expf(dtv * a);
        s = fmaf(s, dA, (dtv * hv) * Bv);

        float p = s * Cv;
#pragma unroll
        for (int off = 8; off; off >>= 1)
            p += __shfl_xor_sync(0xffffffffu, p, off, 16);

        if (n == 0) {
            float g  = xz[(size_t)l * (2 * EQ) + EQ + e];
            float sg = g / (1.f + __expf(-g));
            float v  = (p + hv * d) * sg;
            y[(size_t)l * EQ + e] = __float2half_rn(v);
        }
    }
}

// ---------------------------------------------------------------------------
// Launcher
// ---------------------------------------------------------------------------
typedef CUresult (*PFN_encodeTiled)(
    CUtensorMap*, CUtensorMapDataType, cuuint32_t, void*,
    const cuuint64_t*, const cuuint64_t*, const cuuint32_t*, const cuuint32_t*,
    CUtensorMapInterleave, CUtensorMapSwizzle, CUtensorMapL2promotion,
    CUtensorMapFloatOOBfill);

static void make_tm(PFN_encodeTiled enc, CUtensorMap* tm, void* p,
                    uint64_t rows, uint64_t kelems)
{
    cuuint64_t dims[2]    = {kelems, rows};
    cuuint64_t strides[1] = {kelems * 2};
    cuuint32_t box[2]     = {64, 128};
    cuuint32_t es[2]      = {1, 1};
    enc(tm, CU_TENSOR_MAP_DATA_TYPE_UINT16, 2, p, dims, strides, box, es,
        CU_TENSOR_MAP_INTERLEAVE_NONE, CU_TENSOR_MAP_SWIZZLE_128B,
        CU_TENSOR_MAP_L2_PROMOTION_L2_128B, CU_TENSOR_MAP_FLOAT_OOB_FILL_NONE);
}

static inline void cvt_launch(const float* src, __half* dst, int n)
{
    cvt16_kernel<<<(n / 4 + 255) / 256, 256>>>(
        (const float4*)src, (uint2*)dst, n / 4);
}

extern "C" void kernel_launch(void* const* d_in, const int* in_sizes, int n_in,
                              void* d_out, int out_size)
{
    const float* hidden     = (const float*)d_in[0];
    const float* in_proj_w  = (const float*)d_in[1];
    const float* conv_w     = (const float*)d_in[2];
    const float* conv_b     = (const float*)d_in[3];
    const float* x_proj_w   = (const float*)d_in[4];
    const float* dt_proj_w  = (const float*)d_in[5];
    const float* dt_proj_b  = (const float*)d_in[6];
    const float* A_log      = (const float*)d_in[7];
    const float* Dp         = (const float*)d_in[8];
    const float* out_proj_w = (const float*)d_in[9];
    float* out = (float*)d_out;

    float *xz, *h, *ssmp, *dt, *xpart;
    cudaGetSymbolAddress((void**)&xz,    g_xz);
    cudaGetSymbolAddress((void**)&h,     g_h);
    cudaGetSymbolAddress((void**)&ssmp,  g_ssm);
    cudaGetSymbolAddress((void**)&dt,    g_dt);
    cudaGetSymbolAddress((void**)&xpart, g_xpart);

    __half *hid, *win, *hb, *wx, *dtr, *wdt, *yb, *wout;
    cudaGetSymbolAddress((void**)&hid,  g_hid);
    cudaGetSymbolAddress((void**)&win,  g_win);
    cudaGetSymbolAddress((void**)&hb,   g_hb);
    cudaGetSymbolAddress((void**)&wx,   g_wx);
    cudaGetSymbolAddress((void**)&dtr,  g_dtr);
    cudaGetSymbolAddress((void**)&wdt,  g_wdt);
    cudaGetSymbolAddress((void**)&yb,   g_yb);
    cudaGetSymbolAddress((void**)&wout, g_wout);

    // tensormap encoder via runtime entry point (no -lcuda needed)
    static PFN_encodeTiled enc = nullptr;
    if (!enc) {
        void* fn = nullptr;
        cudaDriverEntryPointQueryResult st;
        cudaGetDriverEntryPointByVersion("cuTensorMapEncodeTiled", &fn, 12000,
                                         cudaEnableDefault, &st);
        enc = (PFN_encodeTiled)fn;
    }

    CUtensorMap tmInA, tmInB, tmXA, tmXB, tmDtA, tmDtB, tmOutA, tmOutB;
    make_tm(enc, &tmInA,  hid,  LQ,     HQ);
    make_tm(enc, &tmInB,  win,  2 * EQ, HQ);
    make_tm(enc, &tmXA,   hb,   LQ,     EQ);
    make_tm(enc, &tmXB,   wx,   PQ,     EQ);
    make_tm(enc, &tmDtA,  dtr,  LQ,     RQ);
    make_tm(enc, &tmDtB,  wdt,  EQ,     RQ);
    make_tm(enc, &tmOutA, yb,   LQ,     EQ);
    make_tm(enc, &tmOutB, wout, HQ,     EQ);

    cudaFuncSetAttribute(gemm_tma<0, false>, cudaFuncAttributeMaxDynamicSharedMemorySize, GEMM_DSMEM);
    cudaFuncSetAttribute(gemm_tma<1, false>, cudaFuncAttributeMaxDynamicSharedMemorySize, GEMM_DSMEM);
    cudaFuncSetAttribute(gemm_tma<0, true>,  cudaFuncAttributeMaxDynamicSharedMemorySize, GEMM_DSMEM);

    // 1) in_proj: [L,H] @ [2E,H]^T -> g_xz [L,2E]
    cvt_launch(hidden, hid, LQ * HQ);
    cvt_launch(in_proj_w, win, 2 * EQ * HQ);
    gemm_tma<0, false><<<dim3(2 * EQ / 128, LQ / 128), 256, GEMM_DSMEM>>>(
        tmInA, tmInB, xz, 2 * EQ, HQ, 2 * EQ, nullptr);

    // 2) conv + SiLU -> g_h (+ fp16 copy)
    conv_silu_kernel<<<dim3(EQ / 256, LQ), 256>>>(xz, conv_w, conv_b, h, hb);

    // 3) x_proj: split-K=4 partials + reduce -> g_ssm [L,160]
    cvt_launch(x_proj_w, wx, PQ * EQ);
    gemm_tma<0, true><<<dim3(2, LQ / 128, 4), 256, GEMM_DSMEM>>>(
        tmXA, tmXB, xpart, PQ, EQ, PQ, nullptr);
    reduce4_kernel<<<(LQ * PQ + 255) / 256, 256>>>(xpart, ssmp, LQ * PQ);

    // 4) dt_proj + softplus -> g_dt [L,E]
    cvt_strided4_kernel<<<(LQ * RQ / 4 + 255) / 256, 256>>>(
        ssmp, (uint2*)dtr, LQ, RQ, PQ);
    cvt_launch(dt_proj_w, wdt, EQ * RQ);
    gemm_tma<1, false><<<dim3(EQ / 128, LQ / 128), 256, GEMM_DSMEM>>>(
        tmDtA, tmDtB, dt, EQ, RQ, EQ, dt_proj_b);

    // 5) selective scan -> yb (fp16)
    scan_kernel<<<EQ / 16, 256>>>(dt, h, ssmp, xz, A_log, Dp, yb);

    // 6) out_proj -> out [L,H]
    cvt_launch(out_proj_w, wout, HQ * EQ);
    gemm_tma<0, false><<<dim3(HQ / 128, LQ / 128), 256, GEMM_DSMEM>>>(
        tmOutA, tmOutB, out, HQ, EQ, HQ, nullptr);
}

// round 8
// speedup vs baseline: 3.5546x; 1.7300x over previous
#include <cuda_runtime.h>
#include <cuda.h>
#include <cuda_fp16.h>
#include <math.h>
#include <stdint.h>

// Problem constants (fixed shapes)
#define LQ 2048
#define HQ 2048
#define EQ 4096
#define NQ 16
#define KQ 4
#define RQ 128
#define PQ 160

// ---------------------------------------------------------------------------
// Scratch (device globals)
// ---------------------------------------------------------------------------
__device__ float g_xz [LQ * 2 * EQ];
__device__ float g_h  [LQ * EQ];
__device__ float g_ssm[LQ * PQ];
__device__ float g_dt [LQ * EQ];
__device__ float g_xpart[4 * LQ * PQ];

// fp16 operands (1-pass rounding; rel_err budget validated R6/R7)
__device__ __align__(256) __half g_hid [LQ * HQ];
__device__ __align__(256) __half g_win [2 * EQ * HQ];
__device__ __align__(256) __half g_hb  [LQ * EQ];
__device__ __align__(256) __half g_wx  [PQ * EQ];
__device__ __align__(256) __half g_dtr [LQ * RQ];
__device__ __align__(256) __half g_wdt [EQ * RQ];
__device__ __align__(256) __half g_yb  [LQ * EQ];
__device__ __align__(256) __half g_wout[HQ * EQ];

// ---------------------------------------------------------------------------
// PTX helpers
// ---------------------------------------------------------------------------
#define MMA_F16(c, A, B)                                                    \
    asm volatile(                                                           \
        "mma.sync.aligned.m16n8k16.row.col.f32.f16.f16.f32 "                \
        "{%0,%1,%2,%3}, {%4,%5,%6,%7}, {%8,%9}, {%0,%1,%2,%3};\n"           \
        : "+f"(c[0]), "+f"(c[1]), "+f"(c[2]), "+f"(c[3])                    \
        : "r"(A[0]), "r"(A[1]), "r"(A[2]), "r"(A[3]), "r"(B[0]), "r"(B[1]))

#define LDSM4(R, a)                                                         \
    asm volatile("ldmatrix.sync.aligned.m8n8.x4.shared.b16 "                \
                 "{%0,%1,%2,%3}, [%4];"                                     \
                 : "=r"((R)[0]), "=r"((R)[1]), "=r"((R)[2]), "=r"((R)[3])   \
                 : "r"(a))

__device__ __forceinline__ uint32_t smem_u32(const void* p) {
    return (uint32_t)__cvta_generic_to_shared(p);
}
__device__ __forceinline__ void mbar_init(uint32_t a, uint32_t cnt) {
    asm volatile("mbarrier.init.shared.b64 [%0], %1;" :: "r"(a), "r"(cnt) : "memory");
}
__device__ __forceinline__ void mbar_expect_tx(uint32_t a, uint32_t bytes) {
    asm volatile("mbarrier.arrive.expect_tx.shared.b64 _, [%0], %1;"
                 :: "r"(a), "r"(bytes) : "memory");
}
__device__ __forceinline__ void mbar_wait(uint32_t a, uint32_t ph) {
    asm volatile("{\n\t.reg .pred P;\n\t"
                 "WL_%=:\n\t"
                 "mbarrier.try_wait.parity.acquire.cta.shared::cta.b64 P, [%0], %1, 0x989680;\n\t"
                 "@P bra WD_%=;\n\tbra WL_%=;\n\tWD_%=:\n\t}"
                 :: "r"(a), "r"(ph) : "memory");
}
__device__ __forceinline__ void tma_load_2d(uint32_t dst, const CUtensorMap* tm,
                                            int cx, int cy, uint32_t mbar) {
    asm volatile(
        "cp.async.bulk.tensor.2d.shared::cluster.global.tile.mbarrier::complete_tx::bytes "
        "[%0], [%1, {%2, %3}], [%4];"
        :: "r"(dst), "l"(tm), "r"(cx), "r"(cy), "r"(mbar) : "memory");
}

// 64B-row swizzle: chunk c of row r stored at chunk (c ^ ((r>>1)&3)).
// Identical to TMA CU_TENSOR_MAP_SWIZZLE_64B on 64B rows, and to the
// cp.async layout validated in R4-R6.
__device__ __forceinline__ uint32_t swz(int row, int c) {
    return (uint32_t)(row * 64 + ((c ^ ((row >> 1) & 3)) << 4));
}

// ---------------------------------------------------------------------------
// TMA tensor-core GEMM: C[M,N] = epi( A[M,K] * B[N,K]^T ), fp16 in fp32 acc
// BM=128, BN=128, BK=32, 256 threads (8 warps 2x4), warp tile 64x32.
// 6 stages x 16KB (A 8K | B 8K), TMA producer (tid 0), prefetch depth 5.
// ---------------------------------------------------------------------------
#define MAT_BYTES 8192
#define STG_BYTES (2 * MAT_BYTES)
#define NSTAGE 6
#define GEMM_DSMEM (NSTAGE * STG_BYTES + 1024)

__device__ __forceinline__ void compute_chunk(
    uint32_t base, float acc[4][4][4], int wm, int wn, int lane)
{
    const uint32_t sA = base;
    const uint32_t sB = base + MAT_BYTES;

#pragma unroll
    for (int ks = 0; ks < 2; ++ks) {
        const int cb = 2 * ks;

        uint32_t Ah[4][4];
        const int rA = lane & 15;
        const int cA = cb + (lane >> 4);
#pragma unroll
        for (int mt = 0; mt < 4; ++mt)
            LDSM4(Ah[mt], sA + swz(wm * 64 + mt * 16 + rA, cA));

        uint32_t Bq[2][4];
        const int rB = ((lane >> 4) << 3) + (lane & 7);
        const int cB = cb + ((lane >> 3) & 1);
#pragma unroll
        for (int p = 0; p < 2; ++p)
            LDSM4(Bq[p], sB + swz(wn * 32 + p * 16 + rB, cB));

#pragma unroll
        for (int mt = 0; mt < 4; ++mt)
#pragma unroll
            for (int p = 0; p < 2; ++p) {
                MMA_F16(acc[mt][2 * p],     Ah[mt], (&Bq[p][0]));
                MMA_F16(acc[mt][2 * p + 1], Ah[mt], (&Bq[p][2]));
            }
    }
}

// EPI: 0 plain store, 1 softplus(x + bias[col]).
// SPLITK: gridDim.z K-partitions, each writing its own partial slab of C.
template <int EPI, bool SPLITK>
__global__ void __launch_bounds__(256, 2)
gemm_tma(const __grid_constant__ CUtensorMap tmA,
         const __grid_constant__ CUtensorMap tmB,
         float* __restrict__ C, int N, int Kdim, int ldc,
         const float* __restrict__ bias)
{
    extern __shared__ __align__(16) char dsm[];
    __shared__ __align__(8) uint64_t s_mb[NSTAGE];

    const uint32_t sbase = (smem_u32(dsm) + 1023u) & ~1023u;
    const int tid  = threadIdx.x;
    const int warp = tid >> 5, lane = tid & 31;
    const int wm = warp >> 2, wn = warp & 3;
    const int bm = blockIdx.y * 128, bn = blockIdx.x * 128;

    const int Kper = SPLITK ? Kdim / gridDim.z : Kdim;
    const int k00  = SPLITK ? blockIdx.z * Kper : 0;
    const int KT   = Kper >> 5;   // BK = 32

    if (tid == 0) {
#pragma unroll
        for (int s = 0; s < NSTAGE; ++s) mbar_init(smem_u32(&s_mb[s]), 1);
        asm volatile("fence.proxy.async.shared::cta;" ::: "memory");
    }
    __syncthreads();

    // prologue: fill up to NSTAGE stages
    if (tid == 0) {
#pragma unroll
        for (int s = 0; s < NSTAGE; ++s) {
            if (s < KT) {
                uint32_t mb = smem_u32(&s_mb[s]);
                mbar_expect_tx(mb, STG_BYTES);
                tma_load_2d(sbase + s * STG_BYTES,             &tmA, k00 + s * 32, bm, mb);
                tma_load_2d(sbase + s * STG_BYTES + MAT_BYTES, &tmB, k00 + s * 32, bn, mb);
            }
        }
    }

    float acc[4][4][4];
#pragma unroll
    for (int mt = 0; mt < 4; ++mt)
#pragma unroll
        for (int nt = 0; nt < 4; ++nt)
#pragma unroll
            for (int q = 0; q < 4; ++q) acc[mt][nt][q] = 0.f;

    for (int kt = 0; kt < KT; ++kt) {
        const int s  = kt % NSTAGE;
        const int ph = (kt / NSTAGE) & 1;
        mbar_wait(smem_u32(&s_mb[s]), ph);

        compute_chunk(sbase + s * STG_BYTES, acc, wm, wn, lane);

        __syncthreads();   // stage s fully consumed by all warps
        if (tid == 0 && kt + NSTAGE < KT) {
            uint32_t mb = smem_u32(&s_mb[s]);
            mbar_expect_tx(mb, STG_BYTES);
            tma_load_2d(sbase + s * STG_BYTES,             &tmA, k00 + (kt + NSTAGE) * 32, bm, mb);
            tma_load_2d(sbase + s * STG_BYTES + MAT_BYTES, &tmB, k00 + (kt + NSTAGE) * 32, bn, mb);
        }
    }

    float* Cout = C;
    if (SPLITK)
        Cout = C + (size_t)blockIdx.z * (size_t)(gridDim.y * 128) * ldc;

    const int g  = lane >> 2;
    const int kp = (lane & 3) << 1;
#pragma unroll
    for (int mt = 0; mt < 4; ++mt) {
        int row = bm + wm * 64 + mt * 16 + g;
#pragma unroll
        for (int nt = 0; nt < 4; ++nt) {
            int col = bn + wn * 32 + nt * 8 + kp;
            if (col < N) {
                float v0 = acc[mt][nt][0], v1 = acc[mt][nt][1];
                float v2 = acc[mt][nt][2], v3 = acc[mt][nt][3];
                if (EPI == 1) {
                    float b0 = bias[col], b1 = bias[col + 1];
                    v0 += b0; v1 += b1; v2 += b0; v3 += b1;
                    v0 = fmaxf(v0, 0.f) + log1pf(__expf(-fabsf(v0)));
                    v1 = fmaxf(v1, 0.f) + log1pf(__expf(-fabsf(v1)));
                    v2 = fmaxf(v2, 0.f) + log1pf(__expf(-fabsf(v2)));
                    v3 = fmaxf(v3, 0.f) + log1pf(__expf(-fabsf(v3)));
                }
                *reinterpret_cast<float2*>(&Cout[(size_t)row * ldc + col]) =
                    make_float2(v0, v1);
                *reinterpret_cast<float2*>(&Cout[(size_t)(row + 8) * ldc + col]) =
                    make_float2(v2, v3);
            }
        }
    }
}

// ---------------------------------------------------------------------------
// split-K reduce for x_proj
// ---------------------------------------------------------------------------
__global__ void __launch_bounds__(256)
reduce4_kernel(const float* __restrict__ part, float* __restrict__ out, int n)
{
    int i = blockIdx.x * 256 + threadIdx.x;
    if (i < n)
        out[i] = part[i] + part[n + i] + part[2 * n + i] + part[3 * n + i];
}

// ---------------------------------------------------------------------------
// fp32 -> fp16 convert (vectorized x4); strided variant for dt rows
// ---------------------------------------------------------------------------
__global__ void __launch_bounds__(256)
cvt16_kernel(const float4* __restrict__ x, uint2* __restrict__ o, int n4)
{
    int i = blockIdx.x * 256 + threadIdx.x;
    if (i < n4) {
        float4 v = x[i];
        __half2 h0 = __halves2half2(__float2half_rn(v.x), __float2half_rn(v.y));
        __half2 h1 = __halves2half2(__float2half_rn(v.z), __float2half_rn(v.w));
        uint2 w;
        w.x = *(uint32_t*)&h0; w.y = *(uint32_t*)&h1;
        o[i] = w;
    }
}

__global__ void __launch_bounds__(256)
cvt_strided4_kernel(const float* __restrict__ x, uint2* __restrict__ o,
                    int rows, int cols, int srcld)
{
    int i = blockIdx.x * 256 + threadIdx.x;
    int c4 = cols >> 2;
    if (i < rows * c4) {
        int r = i / c4, c = (i - r * c4) << 2;
        float4 v = *reinterpret_cast<const float4*>(&x[(size_t)r * srcld + c]);
        __half2 h0 = __halves2half2(__float2half_rn(v.x), __float2half_rn(v.y));
        __half2 h1 = __halves2half2(__float2half_rn(v.z), __float2half_rn(v.w));
        uint2 w;
        w.x = *(uint32_t*)&h0; w.y = *(uint32_t*)&h1;
        o[i] = w;
    }
}

// ---------------------------------------------------------------------------
// Depthwise causal conv (K=4) + bias + SiLU; emits fp32 h AND fp16 copy
// ---------------------------------------------------------------------------
__global__ void __launch_bounds__(256)
conv_silu_kernel(const float* __restrict__ xz, const float* __restrict__ w,
                 const float* __restrict__ b, float* __restrict__ h,
                 __half* __restrict__ hh)
{
    int e = blockIdx.x * 256 + threadIdx.x;
    int l = blockIdx.y;
    float acc = b[e];
#pragma unroll
    for (int k = 0; k < KQ; ++k) {
        int ls = l - (KQ - 1) + k;
        if (ls >= 0)
            acc = fmaf(w[e * KQ + k], xz[(size_t)ls * (2 * EQ) + e], acc);
    }
    float sg = 1.f / (1.f + __expf(-acc));
    float v = acc * sg;
    size_t o = (size_t)l * EQ + e;
    h[o] = v;
    hh[o] = __float2half_rn(v);
}

// ---------------------------------------------------------------------------
// Selective scan with 1-ahead register prefetch; emits gated y as fp16
// ---------------------------------------------------------------------------
__global__ void __launch_bounds__(256)
scan_kernel(const float* __restrict__ dt, const float* __restrict__ h,
            const float* __restrict__ ssm, const float* __restrict__ xz,
            const float* __restrict__ A_log, const float* __restrict__ Dp,
            __half* __restrict__ y)
{
    int tid = threadIdx.x;
    int n   = tid & 15;
    int el  = tid >> 4;
    int e   = blockIdx.x * 16 + el;

    float a = -__expf(A_log[e * NQ + n]);
    float d = Dp[e];
    float s = 0.f;

    // prefetch l = 0
    float dtv = dt[e];
    float hv  = h [e];
    float Bv  = ssm[RQ + n];
    float Cv  = ssm[RQ + NQ + n];
    float gv  = xz[EQ + e];

    for (int l = 0; l < LQ; ++l) {
        float ndt = 0.f, nhv = 0.f, nBv = 0.f, nCv = 0.f, ngv = 0.f;
        if (l + 1 < LQ) {
            size_t o1 = (size_t)(l + 1) * EQ + e;
            ndt = dt[o1];
            nhv = h [o1];
            nBv = ssm[(l + 1) * PQ + RQ + n];
            nCv = ssm[(l + 1) * PQ + RQ + NQ + n];
            ngv = xz[(size_t)(l + 1) * (2 * EQ) + EQ + e];
        }

        float dA = __expf(dtv * a);
        s = fmaf(s, dA, (dtv * hv) * Bv);

        float p = s * Cv;
#pragma unroll
        for (int off = 8; off; off >>= 1)
            p += __shfl_xor_sync(0xffffffffu, p, off, 16);

        if (n == 0) {
            float sg = gv / (1.f + __expf(-gv));
            float v  = (p + hv * d) * sg;
            y[(size_t)l * EQ + e] = __float2half_rn(v);
        }

        dtv = ndt; hv = nhv; Bv = nBv; Cv = nCv; gv = ngv;
    }
}

// ---------------------------------------------------------------------------
// Launcher
// ---------------------------------------------------------------------------
typedef CUresult (*PFN_encodeTiled)(
    CUtensorMap*, CUtensorMapDataType, cuuint32_t, void*,
    const cuuint64_t*, const cuuint64_t*, const cuuint32_t*, const cuuint32_t*,
    CUtensorMapInterleave, CUtensorMapSwizzle, CUtensorMapL2promotion,
    CUtensorMapFloatOOBfill);

static void make_tm(PFN_encodeTiled enc, CUtensorMap* tm, void* p,
                    uint64_t rows, uint64_t kelems)
{
    cuuint64_t dims[2]    = {kelems, rows};
    cuuint64_t strides[1] = {kelems * 2};
    cuuint32_t box[2]     = {32, 128};   // BK=32 fp16 = 64B rows
    cuuint32_t es[2]      = {1, 1};
    enc(tm, CU_TENSOR_MAP_DATA_TYPE_UINT16, 2, p, dims, strides, box, es,
        CU_TENSOR_MAP_INTERLEAVE_NONE, CU_TENSOR_MAP_SWIZZLE_64B,
        CU_TENSOR_MAP_L2_PROMOTION_L2_128B, CU_TENSOR_MAP_FLOAT_OOB_FILL_NONE);
}

static inline void cvt_launch(const float* src, __half* dst, int n)
{
    cvt16_kernel<<<(n / 4 + 255) / 256, 256>>>(
        (const float4*)src, (uint2*)dst, n / 4);
}

extern "C" void kernel_launch(void* const* d_in, const int* in_sizes, int n_in,
                              void* d_out, int out_size)
{
    const float* hidden     = (const float*)d_in[0];
    const float* in_proj_w  = (const float*)d_in[1];
    const float* conv_w     = (const float*)d_in[2];
    const float* conv_b     = (const float*)d_in[3];
    const float* x_proj_w   = (const float*)d_in[4];
    const float* dt_proj_w  = (const float*)d_in[5];
    const float* dt_proj_b  = (const float*)d_in[6];
    const float* A_log      = (const float*)d_in[7];
    const float* Dp         = (const float*)d_in[8];
    const float* out_proj_w = (const float*)d_in[9];
    float* out = (float*)d_out;

    float *xz, *h, *ssmp, *dt, *xpart;
    cudaGetSymbolAddress((void**)&xz,    g_xz);
    cudaGetSymbolAddress((void**)&h,     g_h);
    cudaGetSymbolAddress((void**)&ssmp,  g_ssm);
    cudaGetSymbolAddress((void**)&dt,    g_dt);
    cudaGetSymbolAddress((void**)&xpart, g_xpart);

    __half *hid, *win, *hb, *wx, *dtr, *wdt, *yb, *wout;
    cudaGetSymbolAddress((void**)&hid,  g_hid);
    cudaGetSymbolAddress((void**)&win,  g_win);
    cudaGetSymbolAddress((void**)&hb,   g_hb);
    cudaGetSymbolAddress((void**)&wx,   g_wx);
    cudaGetSymbolAddress((void**)&dtr,  g_dtr);
    cudaGetSymbolAddress((void**)&wdt,  g_wdt);
    cudaGetSymbolAddress((void**)&yb,   g_yb);
    cudaGetSymbolAddress((void**)&wout, g_wout);

    static PFN_encodeTiled enc = nullptr;
    if (!enc) {
        void* fn = nullptr;
        cudaDriverEntryPointQueryResult st;
        cudaGetDriverEntryPointByVersion("cuTensorMapEncodeTiled", &fn, 12000,
                                         cudaEnableDefault, &st);
        enc = (PFN_encodeTiled)fn;
    }

    CUtensorMap tmInA, tmInB, tmXA, tmXB, tmDtA, tmDtB, tmOutA, tmOutB;
    make_tm(enc, &tmInA,  hid,  LQ,     HQ);
    make_tm(enc, &tmInB,  win,  2 * EQ, HQ);
    make_tm(enc, &tmXA,   hb,   LQ,     EQ);
    make_tm(enc, &tmXB,   wx,   PQ,     EQ);
    make_tm(enc, &tmDtA,  dtr,  LQ,     RQ);
    make_tm(enc, &tmDtB,  wdt,  EQ,     RQ);
    make_tm(enc, &tmOutA, yb,   LQ,     EQ);
    make_tm(enc, &tmOutB, wout, HQ,     EQ);

    cudaFuncSetAttribute(gemm_tma<0, false>, cudaFuncAttributeMaxDynamicSharedMemorySize, GEMM_DSMEM);
    cudaFuncSetAttribute(gemm_tma<1, false>, cudaFuncAttributeMaxDynamicSharedMemorySize, GEMM_DSMEM);
    cudaFuncSetAttribute(gemm_tma<0, true>,  cudaFuncAttributeMaxDynamicSharedMemorySize, GEMM_DSMEM);

    // Launches 1-3: converts (cvt(wout) hoisted so gemm_in is launch #4 -> ncu)
    cvt_launch(hidden, hid, LQ * HQ);          // 1
    cvt_launch(in_proj_w, win, 2 * EQ * HQ);   // 2
    cvt_launch(out_proj_w, wout, HQ * EQ);     // 3

    // 4) in_proj: [L,H] @ [2E,H]^T -> g_xz [L,2E]   <- ncu profiles this
    gemm_tma<0, false><<<dim3(2 * EQ / 128, LQ / 128), 256, GEMM_DSMEM>>>(
        tmInA, tmInB, xz, 2 * EQ, HQ, 2 * EQ, nullptr);

    // 5) conv + SiLU -> g_h (+ fp16 copy)
    conv_silu_kernel<<<dim3(EQ / 256, LQ), 256>>>(xz, conv_w, conv_b, h, hb);

    // 6-8) x_proj: split-K=4 partials + reduce -> g_ssm [L,160]
    cvt_launch(x_proj_w, wx, PQ * EQ);
    gemm_tma<0, true><<<dim3(2, LQ / 128, 4), 256, GEMM_DSMEM>>>(
        tmXA, tmXB, xpart, PQ, EQ, PQ, nullptr);
    reduce4_kernel<<<(LQ * PQ + 255) / 256, 256>>>(xpart, ssmp, LQ * PQ);

    // 9-11) dt_proj + softplus -> g_dt [L,E]
    cvt_strided4_kernel<<<(LQ * RQ / 4 + 255) / 256, 256>>>(
        ssmp, (uint2*)dtr, LQ, RQ, PQ);
    cvt_launch(dt_proj_w, wdt, EQ * RQ);
    gemm_tma<1, false><<<dim3(EQ / 128, LQ / 128), 256, GEMM_DSMEM>>>(
        tmDtA, tmDtB, dt, EQ, RQ, EQ, dt_proj_b);

    // 12) selective scan -> yb (fp16)
    scan_kernel<<<EQ / 16, 256>>>(dt, h, ssmp, xz, A_log, Dp, yb);

    // 13) out_proj -> out [L,H]
    gemm_tma<0, false><<<dim3(HQ / 128, LQ / 128), 256, GEMM_DSMEM>>>(
        tmOutA, tmOutB, out, HQ, EQ, HQ, nullptr);
}

// round 9
// speedup vs baseline: 5.1269x; 1.4423x over previous
#include <cuda_runtime.h>
#include <cuda.h>
#include <cuda_fp16.h>
#include <math.h>
#include <stdint.h>

// Problem constants (fixed shapes)
#define LQ 2048
#define HQ 2048
#define EQ 4096
#define NQ 16
#define KQ 4
#define RQ 128
#define PQ 160

// scan chunking
#define CH 16            // number of chunks
#define CL (LQ / CH)     // 128 steps per chunk

// ---------------------------------------------------------------------------
// Scratch (device globals)
// ---------------------------------------------------------------------------
__device__ float g_xz [LQ * 2 * EQ];
__device__ float g_h  [LQ * EQ];
__device__ float g_ssm[LQ * PQ];
__device__ float g_dt [LQ * EQ];
__device__ float g_xpart[4 * LQ * PQ];
__device__ float g_P[EQ * NQ * CH];   // per-chunk decay products
__device__ float g_q[EQ * NQ * CH];   // per-chunk local final states

// fp16 operands (1-pass rounding; rel_err budget validated R6-R8)
__device__ __align__(256) __half g_hid [LQ * HQ];
__device__ __align__(256) __half g_win [2 * EQ * HQ];
__device__ __align__(256) __half g_hb  [LQ * EQ];
__device__ __align__(256) __half g_wx  [PQ * EQ];
__device__ __align__(256) __half g_dtr [LQ * RQ];
__device__ __align__(256) __half g_wdt [EQ * RQ];
__device__ __align__(256) __half g_yb  [LQ * EQ];
__device__ __align__(256) __half g_wout[HQ * EQ];

// ---------------------------------------------------------------------------
// PTX helpers
// ---------------------------------------------------------------------------
#define MMA_F16(c, A, B)                                                    \
    asm volatile(                                                           \
        "mma.sync.aligned.m16n8k16.row.col.f32.f16.f16.f32 "                \
        "{%0,%1,%2,%3}, {%4,%5,%6,%7}, {%8,%9}, {%0,%1,%2,%3};\n"           \
        : "+f"(c[0]), "+f"(c[1]), "+f"(c[2]), "+f"(c[3])                    \
        : "r"(A[0]), "r"(A[1]), "r"(A[2]), "r"(A[3]), "r"(B[0]), "r"(B[1]))

#define LDSM4(R, a)                                                         \
    asm volatile("ldmatrix.sync.aligned.m8n8.x4.shared.b16 "                \
                 "{%0,%1,%2,%3}, [%4];"                                     \
                 : "=r"((R)[0]), "=r"((R)[1]), "=r"((R)[2]), "=r"((R)[3])   \
                 : "r"(a))

__device__ __forceinline__ uint32_t smem_u32(const void* p) {
    return (uint32_t)__cvta_generic_to_shared(p);
}
__device__ __forceinline__ void mbar_init(uint32_t a, uint32_t cnt) {
    asm volatile("mbarrier.init.shared.b64 [%0], %1;" :: "r"(a), "r"(cnt) : "memory");
}
__device__ __forceinline__ void mbar_expect_tx(uint32_t a, uint32_t bytes) {
    asm volatile("mbarrier.arrive.expect_tx.shared.b64 _, [%0], %1;"
                 :: "r"(a), "r"(bytes) : "memory");
}
__device__ __forceinline__ void mbar_wait(uint32_t a, uint32_t ph) {
    asm volatile("{\n\t.reg .pred P;\n\t"
                 "WL_%=:\n\t"
                 "mbarrier.try_wait.parity.acquire.cta.shared::cta.b64 P, [%0], %1, 0x989680;\n\t"
                 "@P bra WD_%=;\n\tbra WL_%=;\n\tWD_%=:\n\t}"
                 :: "r"(a), "r"(ph) : "memory");
}
__device__ __forceinline__ void tma_load_2d(uint32_t dst, const CUtensorMap* tm,
                                            int cx, int cy, uint32_t mbar) {
    asm volatile(
        "cp.async.bulk.tensor.2d.shared::cluster.global.tile.mbarrier::complete_tx::bytes "
        "[%0], [%1, {%2, %3}], [%4];"
        :: "r"(dst), "l"(tm), "r"(cx), "r"(cy), "r"(mbar) : "memory");
}

// 64B-row swizzle == TMA CU_TENSOR_MAP_SWIZZLE_64B (validated R8)
__device__ __forceinline__ uint32_t swz(int row, int c) {
    return (uint32_t)(row * 64 + ((c ^ ((row >> 1) & 3)) << 4));
}

// ---------------------------------------------------------------------------
// TMA tensor-core GEMM: C[M,N] = epi( A[M,K] * B[N,K]^T ), fp16 in fp32 acc
// BM=128, BN=128, BK=32, 256 threads (8 warps 2x4), warp tile 64x32.
// 6 stages x 16KB, TMA producer (tid 0), prefetch depth 5.  (validated R8)
// ---------------------------------------------------------------------------
#define MAT_BYTES 8192
#define STG_BYTES (2 * MAT_BYTES)
#define NSTAGE 6
#define GEMM_DSMEM (NSTAGE * STG_BYTES + 1024)

__device__ __forceinline__ void compute_chunk(
    uint32_t base, float acc[4][4][4], int wm, int wn, int lane)
{
    const uint32_t sA = base;
    const uint32_t sB = base + MAT_BYTES;

#pragma unroll
    for (int ks = 0; ks < 2; ++ks) {
        const int cb = 2 * ks;

        uint32_t Ah[4][4];
        const int rA = lane & 15;
        const int cA = cb + (lane >> 4);
#pragma unroll
        for (int mt = 0; mt < 4; ++mt)
            LDSM4(Ah[mt], sA + swz(wm * 64 + mt * 16 + rA, cA));

        uint32_t Bq[2][4];
        const int rB = ((lane >> 4) << 3) + (lane & 7);
        const int cB = cb + ((lane >> 3) & 1);
#pragma unroll
        for (int p = 0; p < 2; ++p)
            LDSM4(Bq[p], sB + swz(wn * 32 + p * 16 + rB, cB));

#pragma unroll
        for (int mt = 0; mt < 4; ++mt)
#pragma unroll
            for (int p = 0; p < 2; ++p) {
                MMA_F16(acc[mt][2 * p],     Ah[mt], (&Bq[p][0]));
                MMA_F16(acc[mt][2 * p + 1], Ah[mt], (&Bq[p][2]));
            }
    }
}

template <int EPI, bool SPLITK>
__global__ void __launch_bounds__(256, 2)
gemm_tma(const __grid_constant__ CUtensorMap tmA,
         const __grid_constant__ CUtensorMap tmB,
         float* __restrict__ C, int N, int Kdim, int ldc,
         const float* __restrict__ bias)
{
    extern __shared__ __align__(16) char dsm[];
    __shared__ __align__(8) uint64_t s_mb[NSTAGE];

    const uint32_t sbase = (smem_u32(dsm) + 1023u) & ~1023u;
    const int tid  = threadIdx.x;
    const int warp = tid >> 5, lane = tid & 31;
    const int wm = warp >> 2, wn = warp & 3;
    const int bm = blockIdx.y * 128, bn = blockIdx.x * 128;

    const int Kper = SPLITK ? Kdim / gridDim.z : Kdim;
    const int k00  = SPLITK ? blockIdx.z * Kper : 0;
    const int KT   = Kper >> 5;   // BK = 32

    if (tid == 0) {
#pragma unroll
        for (int s = 0; s < NSTAGE; ++s) mbar_init(smem_u32(&s_mb[s]), 1);
        asm volatile("fence.proxy.async.shared::cta;" ::: "memory");
    }
    __syncthreads();

    if (tid == 0) {
#pragma unroll
        for (int s = 0; s < NSTAGE; ++s) {
            if (s < KT) {
                uint32_t mb = smem_u32(&s_mb[s]);
                mbar_expect_tx(mb, STG_BYTES);
                tma_load_2d(sbase + s * STG_BYTES,             &tmA, k00 + s * 32, bm, mb);
                tma_load_2d(sbase + s * STG_BYTES + MAT_BYTES, &tmB, k00 + s * 32, bn, mb);
            }
        }
    }

    float acc[4][4][4];
#pragma unroll
    for (int mt = 0; mt < 4; ++mt)
#pragma unroll
        for (int nt = 0; nt < 4; ++nt)
#pragma unroll
            for (int q = 0; q < 4; ++q) acc[mt][nt][q] = 0.f;

    for (int kt = 0; kt < KT; ++kt) {
        const int s  = kt % NSTAGE;
        const int ph = (kt / NSTAGE) & 1;
        mbar_wait(smem_u32(&s_mb[s]), ph);

        compute_chunk(sbase + s * STG_BYTES, acc, wm, wn, lane);

        __syncthreads();
        if (tid == 0 && kt + NSTAGE < KT) {
            uint32_t mb = smem_u32(&s_mb[s]);
            mbar_expect_tx(mb, STG_BYTES);
            tma_load_2d(sbase + s * STG_BYTES,             &tmA, k00 + (kt + NSTAGE) * 32, bm, mb);
            tma_load_2d(sbase + s * STG_BYTES + MAT_BYTES, &tmB, k00 + (kt + NSTAGE) * 32, bn, mb);
        }
    }

    float* Cout = C;
    if (SPLITK)
        Cout = C + (size_t)blockIdx.z * (size_t)(gridDim.y * 128) * ldc;

    const int g  = lane >> 2;
    const int kp = (lane & 3) << 1;
#pragma unroll
    for (int mt = 0; mt < 4; ++mt) {
        int row = bm + wm * 64 + mt * 16 + g;
#pragma unroll
        for (int nt = 0; nt < 4; ++nt) {
            int col = bn + wn * 32 + nt * 8 + kp;
            if (col < N) {
                float v0 = acc[mt][nt][0], v1 = acc[mt][nt][1];
                float v2 = acc[mt][nt][2], v3 = acc[mt][nt][3];
                if (EPI == 1) {
                    float b0 = bias[col], b1 = bias[col + 1];
                    v0 += b0; v1 += b1; v2 += b0; v3 += b1;
                    v0 = fmaxf(v0, 0.f) + log1pf(__expf(-fabsf(v0)));
                    v1 = fmaxf(v1, 0.f) + log1pf(__expf(-fabsf(v1)));
                    v2 = fmaxf(v2, 0.f) + log1pf(__expf(-fabsf(v2)));
                    v3 = fmaxf(v3, 0.f) + log1pf(__expf(-fabsf(v3)));
                }
                *reinterpret_cast<float2*>(&Cout[(size_t)row * ldc + col]) =
                    make_float2(v0, v1);
                *reinterpret_cast<float2*>(&Cout[(size_t)(row + 8) * ldc + col]) =
                    make_float2(v2, v3);
            }
        }
    }
}

// ---------------------------------------------------------------------------
// split-K reduce for x_proj
// ---------------------------------------------------------------------------
__global__ void __launch_bounds__(256)
reduce4_kernel(const float* __restrict__ part, float* __restrict__ out, int n)
{
    int i = blockIdx.x * 256 + threadIdx.x;
    if (i < n)
        out[i] = part[i] + part[n + i] + part[2 * n + i] + part[3 * n + i];
}

// ---------------------------------------------------------------------------
// fp32 -> fp16 convert (vectorized x4); strided variant for dt rows
// ---------------------------------------------------------------------------
__global__ void __launch_bounds__(256)
cvt16_kernel(const float4* __restrict__ x, uint2* __restrict__ o, int n4)
{
    int i = blockIdx.x * 256 + threadIdx.x;
    if (i < n4) {
        float4 v = x[i];
        __half2 h0 = __halves2half2(__float2half_rn(v.x), __float2half_rn(v.y));
        __half2 h1 = __halves2half2(__float2half_rn(v.z), __float2half_rn(v.w));
        uint2 w;
        w.x = *(uint32_t*)&h0; w.y = *(uint32_t*)&h1;
        o[i] = w;
    }
}

__global__ void __launch_bounds__(256)
cvt_strided4_kernel(const float* __restrict__ x, uint2* __restrict__ o,
                    int rows, int cols, int srcld)
{
    int i = blockIdx.x * 256 + threadIdx.x;
    int c4 = cols >> 2;
    if (i < rows * c4) {
        int r = i / c4, c = (i - r * c4) << 2;
        float4 v = *reinterpret_cast<const float4*>(&x[(size_t)r * srcld + c]);
        __half2 h0 = __halves2half2(__float2half_rn(v.x), __float2half_rn(v.y));
        __half2 h1 = __halves2half2(__float2half_rn(v.z), __float2half_rn(v.w));
        uint2 w;
        w.x = *(uint32_t*)&h0; w.y = *(uint32_t*)&h1;
        o[i] = w;
    }
}

// ---------------------------------------------------------------------------
// Depthwise causal conv (K=4) + bias + SiLU; emits fp32 h AND fp16 copy
// ---------------------------------------------------------------------------
__global__ void __launch_bounds__(256)
conv_silu_kernel(const float* __restrict__ xz, const float* __restrict__ w,
                 const float* __restrict__ b, float* __restrict__ h,
                 __half* __restrict__ hh)
{
    int e = blockIdx.x * 256 + threadIdx.x;
    int l = blockIdx.y;
    float acc = b[e];
#pragma unroll
    for (int k = 0; k < KQ; ++k) {
        int ls = l - (KQ - 1) + k;
        if (ls >= 0)
            acc = fmaf(w[e * KQ + k], xz[(size_t)ls * (2 * EQ) + e], acc);
    }
    float sg = 1.f / (1.f + __expf(-acc));
    float v = acc * sg;
    size_t o = (size_t)l * EQ + e;
    h[o] = v;
    hh[o] = __float2half_rn(v);
}

// ---------------------------------------------------------------------------
// Chunked selective scan (pass 1): per (e, n, chunk) compute
//   P = prod_{l in chunk} dA_l,   q = chunk-local final state (s0 = 0)
// Block = 16 e x 16 n; grid = (E/16, CH).
// ---------------------------------------------------------------------------
__global__ void __launch_bounds__(256)
scan1_kernel(const float* __restrict__ dt, const float* __restrict__ h,
             const float* __restrict__ ssm, const float* __restrict__ A_log,
             float* __restrict__ gP, float* __restrict__ gq)
{
    int tid = threadIdx.x;
    int n   = tid & 15;
    int el  = tid >> 4;
    int e   = blockIdx.x * 16 + el;
    int c   = blockIdx.y;
    int l0  = c * CL;

    float a = -__expf(A_log[e * NQ + n]);
    float P = 1.f, s = 0.f;

    for (int l = l0; l < l0 + CL; ++l) {
        float dtv = dt[(size_t)l * EQ + e];
        float hv  = h [(size_t)l * EQ + e];
        float Bv  = ssm[l * PQ + RQ + n];
        float dA  = __expf(dtv * a);
        s = fmaf(s, dA, (dtv * hv) * Bv);
        P *= dA;
    }
    int idx = (e * NQ + n) * CH + c;
    gP[idx] = P;
    gq[idx] = s;
}

// ---------------------------------------------------------------------------
// Chunked selective scan (pass 2): fold prefix (P,q) to get s_start, replay
// the chunk emitting y[l,e] = (sum_n s*C + h*D) * silu(gate), as fp16.
// ---------------------------------------------------------------------------
__global__ void __launch_bounds__(256)
scan2_kernel(const float* __restrict__ dt, const float* __restrict__ h,
             const float* __restrict__ ssm, const float* __restrict__ xz,
             const float* __restrict__ A_log, const float* __restrict__ Dp,
             const float* __restrict__ gP, const float* __restrict__ gq,
             __half* __restrict__ y)
{
    int tid = threadIdx.x;
    int n   = tid & 15;
    int el  = tid >> 4;
    int e   = blockIdx.x * 16 + el;
    int c   = blockIdx.y;
    int l0  = c * CL;

    float a = -__expf(A_log[e * NQ + n]);
    float d = Dp[e];

    // fold preceding chunks: s = ((q0)*P1+q1)*P2+q2 ...
    float s = 0.f;
    int base = (e * NQ + n) * CH;
    for (int cc = 0; cc < c; ++cc)
        s = fmaf(s, gP[base + cc], gq[base + cc]);

    for (int l = l0; l < l0 + CL; ++l) {
        float dtv = dt[(size_t)l * EQ + e];
        float hv  = h [(size_t)l * EQ + e];
        float Bv  = ssm[l * PQ + RQ + n];
        float Cv  = ssm[l * PQ + RQ + NQ + n];

        float dA = __expf(dtv * a);
        s = fmaf(s, dA, (dtv * hv) * Bv);

        float p = s * Cv;
#pragma unroll
        for (int off = 8; off; off >>= 1)
            p += __shfl_xor_sync(0xffffffffu, p, off, 16);

        if (n == 0) {
            float g  = xz[(size_t)l * (2 * EQ) + EQ + e];
            float sg = g / (1.f + __expf(-g));
            float v  = (p + hv * d) * sg;
            y[(size_t)l * EQ + e] = __float2half_rn(v);
        }
    }
}

// ---------------------------------------------------------------------------
// Launcher
// ---------------------------------------------------------------------------
typedef CUresult (*PFN_encodeTiled)(
    CUtensorMap*, CUtensorMapDataType, cuuint32_t, void*,
    const cuuint64_t*, const cuuint64_t*, const cuuint32_t*, const cuuint32_t*,
    CUtensorMapInterleave, CUtensorMapSwizzle, CUtensorMapL2promotion,
    CUtensorMapFloatOOBfill);

static void make_tm(PFN_encodeTiled enc, CUtensorMap* tm, void* p,
                    uint64_t rows, uint64_t kelems)
{
    cuuint64_t dims[2]    = {kelems, rows};
    cuuint64_t strides[1] = {kelems * 2};
    cuuint32_t box[2]     = {32, 128};   // BK=32 fp16 = 64B rows
    cuuint32_t es[2]      = {1, 1};
    enc(tm, CU_TENSOR_MAP_DATA_TYPE_UINT16, 2, p, dims, strides, box, es,
        CU_TENSOR_MAP_INTERLEAVE_NONE, CU_TENSOR_MAP_SWIZZLE_64B,
        CU_TENSOR_MAP_L2_PROMOTION_L2_128B, CU_TENSOR_MAP_FLOAT_OOB_FILL_NONE);
}

static inline void cvt_launch(const float* src, __half* dst, int n)
{
    cvt16_kernel<<<(n / 4 + 255) / 256, 256>>>(
        (const float4*)src, (uint2*)dst, n / 4);
}

extern "C" void kernel_launch(void* const* d_in, const int* in_sizes, int n_in,
                              void* d_out, int out_size)
{
    const float* hidden     = (const float*)d_in[0];
    const float* in_proj_w  = (const float*)d_in[1];
    const float* conv_w     = (const float*)d_in[2];
    const float* conv_b     = (const float*)d_in[3];
    const float* x_proj_w   = (const float*)d_in[4];
    const float* dt_proj_w  = (const float*)d_in[5];
    const float* dt_proj_b  = (const float*)d_in[6];
    const float* A_log      = (const float*)d_in[7];
    const float* Dp         = (const float*)d_in[8];
    const float* out_proj_w = (const float*)d_in[9];
    float* out = (float*)d_out;

    float *xz, *h, *ssmp, *dt, *xpart, *gP, *gq;
    cudaGetSymbolAddress((void**)&xz,    g_xz);
    cudaGetSymbolAddress((void**)&h,     g_h);
    cudaGetSymbolAddress((void**)&ssmp,  g_ssm);
    cudaGetSymbolAddress((void**)&dt,    g_dt);
    cudaGetSymbolAddress((void**)&xpart, g_xpart);
    cudaGetSymbolAddress((void**)&gP,    g_P);
    cudaGetSymbolAddress((void**)&gq,    g_q);

    __half *hid, *win, *hb, *wx, *dtr, *wdt, *yb, *wout;
    cudaGetSymbolAddress((void**)&hid,  g_hid);
    cudaGetSymbolAddress((void**)&win,  g_win);
    cudaGetSymbolAddress((void**)&hb,   g_hb);
    cudaGetSymbolAddress((void**)&wx,   g_wx);
    cudaGetSymbolAddress((void**)&dtr,  g_dtr);
    cudaGetSymbolAddress((void**)&wdt,  g_wdt);
    cudaGetSymbolAddress((void**)&yb,   g_yb);
    cudaGetSymbolAddress((void**)&wout, g_wout);

    static PFN_encodeTiled enc = nullptr;
    if (!enc) {
        void* fn = nullptr;
        cudaDriverEntryPointQueryResult st;
        cudaGetDriverEntryPointByVersion("cuTensorMapEncodeTiled", &fn, 12000,
                                         cudaEnableDefault, &st);
        enc = (PFN_encodeTiled)fn;
    }

    CUtensorMap tmInA, tmInB, tmXA, tmXB, tmDtA, tmDtB, tmOutA, tmOutB;
    make_tm(enc, &tmInA,  hid,  LQ,     HQ);
    make_tm(enc, &tmInB,  win,  2 * EQ, HQ);
    make_tm(enc, &tmXA,   hb,   LQ,     EQ);
    make_tm(enc, &tmXB,   wx,   PQ,     EQ);
    make_tm(enc, &tmDtA,  dtr,  LQ,     RQ);
    make_tm(enc, &tmDtB,  wdt,  EQ,     RQ);
    make_tm(enc, &tmOutA, yb,   LQ,     EQ);
    make_tm(enc, &tmOutB, wout, HQ,     EQ);

    cudaFuncSetAttribute(gemm_tma<0, false>, cudaFuncAttributeMaxDynamicSharedMemorySize, GEMM_DSMEM);
    cudaFuncSetAttribute(gemm_tma<1, false>, cudaFuncAttributeMaxDynamicSharedMemorySize, GEMM_DSMEM);
    cudaFuncSetAttribute(gemm_tma<0, true>,  cudaFuncAttributeMaxDynamicSharedMemorySize, GEMM_DSMEM);

    // 1-3) converts
    cvt_launch(hidden, hid, LQ * HQ);
    cvt_launch(in_proj_w, win, 2 * EQ * HQ);
    cvt_launch(out_proj_w, wout, HQ * EQ);

    // 4) in_proj: [L,H] @ [2E,H]^T -> g_xz [L,2E]
    gemm_tma<0, false><<<dim3(2 * EQ / 128, LQ / 128), 256, GEMM_DSMEM>>>(
        tmInA, tmInB, xz, 2 * EQ, HQ, 2 * EQ, nullptr);

    // 5) conv + SiLU -> g_h (+ fp16 copy)
    conv_silu_kernel<<<dim3(EQ / 256, LQ), 256>>>(xz, conv_w, conv_b, h, hb);

    // 6-8) x_proj: split-K=4 partials + reduce -> g_ssm [L,160]
    cvt_launch(x_proj_w, wx, PQ * EQ);
    gemm_tma<0, true><<<dim3(2, LQ / 128, 4), 256, GEMM_DSMEM>>>(
        tmXA, tmXB, xpart, PQ, EQ, PQ, nullptr);
    reduce4_kernel<<<(LQ * PQ + 255) / 256, 256>>>(xpart, ssmp, LQ * PQ);

    // 9-11) dt_proj + softplus -> g_dt [L,E]
    cvt_strided4_kernel<<<(LQ * RQ / 4 + 255) / 256, 256>>>(
        ssmp, (uint2*)dtr, LQ, RQ, PQ);
    cvt_launch(dt_proj_w, wdt, EQ * RQ);
    gemm_tma<1, false><<<dim3(EQ / 128, LQ / 128), 256, GEMM_DSMEM>>>(
        tmDtA, tmDtB, dt, EQ, RQ, EQ, dt_proj_b);

    // 12-13) chunked selective scan -> yb (fp16)
    scan1_kernel<<<dim3(EQ / 16, CH), 256>>>(dt, h, ssmp, A_log, gP, gq);
    scan2_kernel<<<dim3(EQ / 16, CH), 256>>>(dt, h, ssmp, xz, A_log, Dp,
                                             gP, gq, yb);

    // 14) out_proj -> out [L,H]
    gemm_tma<0, false><<<dim3(HQ / 128, LQ / 128), 256, GEMM_DSMEM>>>(
        tmOutA, tmOutB, out, HQ, EQ, HQ, nullptr);
}